// round 11
// baseline (speedup 1.0000x reference)
#include <cuda_runtime.h>
#include <math.h>
#include <stdint.h>

#define BSZ 2
#define SEQ 2048
#define DIM 1024
#define NH  16
#define DK  64
#define BH  (BSZ*NH)   // 32
#define MTOT (BSZ*SEQ) // 4096
#define NROWS (BH*SEQ) // 65536
#define NCT  16        // col tiles of 128 per row

// Scratch (allocation-free rule: __device__ globals)
__device__ float g_q [BSZ*SEQ*DIM];
__device__ float g_k [BSZ*SEQ*DIM];
__device__ float g_v [BSZ*SEQ*DIM];
__device__ float g_bl[BSZ*SEQ*DIM];
__device__ float g_rq[BSZ*SEQ*DIM];     // tf32-rounded inputs
__device__ float g_rk[BSZ*SEQ*DIM];
__device__ float g_rv[BSZ*SEQ*DIM];
__device__ float g_w [4*DIM*DIM];       // tf32-rounded weights
__device__ float g_smax  [NROWS*NCT];
__device__ float g_ssum  [NROWS*NCT];
__device__ float g_factor[NROWS*NCT];

// ---------------------------------------------------------------------------
// helpers
// ---------------------------------------------------------------------------
__device__ __forceinline__ unsigned f2tf(float x) {
    unsigned r;
    asm("cvt.rna.tf32.f32 %0, %1;" : "=r"(r) : "f"(x));
    return r;
}

__device__ __forceinline__ void mma_tf32(float c[4],
    unsigned a0, unsigned a1, unsigned a2, unsigned a3,
    unsigned b0, unsigned b1)
{
    asm volatile(
        "mma.sync.aligned.m16n8k8.row.col.f32.tf32.tf32.f32 "
        "{%0,%1,%2,%3}, {%4,%5,%6,%7}, {%8,%9}, {%0,%1,%2,%3};\n"
        : "+f"(c[0]), "+f"(c[1]), "+f"(c[2]), "+f"(c[3])
        : "r"(a0), "r"(a1), "r"(a2), "r"(a3), "r"(b0), "r"(b1));
}

__device__ __forceinline__ unsigned smem_u32(const void* p) {
    unsigned a;
    asm("{ .reg .u64 t; cvta.to.shared.u64 t, %1; cvt.u32.u64 %0, t; }"
        : "=r"(a) : "l"(p));
    return a;
}

#define CPA_COMMIT() asm volatile("cp.async.commit_group;" ::: "memory")
#define CPA_WAIT1()  asm volatile("cp.async.wait_group 1;" ::: "memory")
#define CPA_WAIT0()  asm volatile("cp.async.wait_group 0;" ::: "memory")

__device__ __forceinline__ void cpa16(const void* smem_dst, const float* gsrc) {
    unsigned sa = smem_u32(smem_dst);
    asm volatile("cp.async.cg.shared.global [%0], [%1], 16;"
                 :: "r"(sa), "l"(gsrc) : "memory");
}

// ---------------------------------------------------------------------------
// pre-round kernels (tf32 bits, idempotent w.r.t. later MMA use)
// ---------------------------------------------------------------------------
__global__ __launch_bounds__(256) void round3(
    const float* __restrict__ a, const float* __restrict__ b,
    const float* __restrict__ c,
    float* __restrict__ da, float* __restrict__ db, float* __restrict__ dc)
{
    const float* s; float* d;
    if      (blockIdx.y == 0) { s = a; d = da; }
    else if (blockIdx.y == 1) { s = b; d = db; }
    else                      { s = c; d = dc; }
    int i = blockIdx.x * 256 + threadIdx.x;
    float4 v = ((const float4*)s)[i];
    uint4 o = make_uint4(f2tf(v.x), f2tf(v.y), f2tf(v.z), f2tf(v.w));
    ((uint4*)d)[i] = o;
}

__global__ __launch_bounds__(256) void round4(
    const float* __restrict__ a, const float* __restrict__ b,
    const float* __restrict__ c, const float* __restrict__ d,
    float* __restrict__ dst)
{
    const float* s;
    if      (blockIdx.y == 0) s = a;
    else if (blockIdx.y == 1) s = b;
    else if (blockIdx.y == 2) s = c;
    else                      s = d;
    int i = blockIdx.x * 256 + threadIdx.x;
    float4 v = ((const float4*)s)[i];
    uint4 o = make_uint4(f2tf(v.x), f2tf(v.y), f2tf(v.z), f2tf(v.w));
    ((uint4*)(dst + (size_t)blockIdx.y * DIM * DIM))[i] = o;
}

// ---------------------------------------------------------------------------
#define TPAD 20   // floats per padded row in GEMM tiles

__device__ __forceinline__ void cpa_tile(
    float (*dst)[TPAD], const float* __restrict__ src, int lda, int tid)
{
    #pragma unroll
    for (int i = 0; i < 2; i++) {
        int id = tid + i * 256;       // 0..511
        int r  = id >> 2;             // 0..127
        int c4 = (id & 3) << 2;       // 0,4,8,12
        cpa16(&dst[r][c4], src + (size_t)r * lda + c4);
    }
}

// One 16-K tile of MMAs; inputs are PRE-ROUNDED tf32 bits (no cvt).
__device__ __forceinline__ void tile_mma(
    const float (*As)[TPAD], const float (*Bs)[TPAD],
    float acc[4][4][4], int wm, int wn, int grp, int qd)
{
    #pragma unroll
    for (int kk = 0; kk < 16; kk += 8) {
        unsigned a[4][4], b[4][2];
        #pragma unroll
        for (int mi = 0; mi < 4; mi++) {
            int m = wm * 64 + mi * 16;
            a[mi][0] = __float_as_uint(As[m + grp    ][kk + qd    ]);
            a[mi][1] = __float_as_uint(As[m + grp + 8][kk + qd    ]);
            a[mi][2] = __float_as_uint(As[m + grp    ][kk + qd + 4]);
            a[mi][3] = __float_as_uint(As[m + grp + 8][kk + qd + 4]);
        }
        #pragma unroll
        for (int ni = 0; ni < 4; ni++) {
            int n = wn * 32 + ni * 8 + grp;
            b[ni][0] = __float_as_uint(Bs[n][kk + qd    ]);
            b[ni][1] = __float_as_uint(Bs[n][kk + qd + 4]);
        }
        #pragma unroll
        for (int mi = 0; mi < 4; mi++)
            #pragma unroll
            for (int ni = 0; ni < 4; ni++)
                mma_tf32(acc[mi][ni], a[mi][0], a[mi][1], a[mi][2], a[mi][3],
                         b[ni][0], b[ni][1]);
    }
}

// 3-stage cp.async mainloop over nk 16-K tiles (nk >= 3).
__device__ __forceinline__ void cpa_loop(
    const float* __restrict__ A, int lda,
    const float* __restrict__ B, int ldb, int nk,
    float (*As)[128][TPAD], float (*Bs)[128][TPAD],
    float acc[4][4][4], int tid, int wm, int wn, int grp, int qd)
{
    cpa_tile(As[0], A, lda, tid);
    cpa_tile(Bs[0], B, ldb, tid);
    CPA_COMMIT();
    cpa_tile(As[1], A + 16, lda, tid);
    cpa_tile(Bs[1], B + 16, ldb, tid);
    CPA_COMMIT();

    int cur = 0;
    for (int t = 0; t < nk; t++) {
        if (t < nk - 1) CPA_WAIT1(); else CPA_WAIT0();
        __syncthreads();
        tile_mma(As[cur], Bs[cur], acc, wm, wn, grp, qd);
        if (t + 2 < nk) {
            int nxt = cur + 2; if (nxt >= 3) nxt -= 3;
            cpa_tile(As[nxt], A + (t + 2) * 16, lda, tid);
            cpa_tile(Bs[nxt], B + (t + 2) * 16, ldb, tid);
            CPA_COMMIT();
        }
        if (++cur == 3) cur = 0;
    }
}

#define GEMM_SMEM (3 * 128 * TPAD * 4 * 2)          // 61440

// ---------------------------------------------------------------------------
// GEMM: C[M,N] = A[M,K] @ W[N,K]^T + bias[N]; A,W pre-rounded tf32 bits.
// ---------------------------------------------------------------------------
__global__ __launch_bounds__(256, 2) void gemm_cpa(
    const float* __restrict__ A, const float* __restrict__ W,
    const float* __restrict__ bias, float* __restrict__ C,
    int M, int N, int K, int round_out)
{
    extern __shared__ float sm[];
    float (*As)[128][TPAD] = (float (*)[128][TPAD])sm;
    float (*Bs)[128][TPAD] = (float (*)[128][TPAD])(sm + 3 * 128 * TPAD);

    int tid = threadIdx.x;
    int warp = tid >> 5, lane = tid & 31;
    int wm = warp >> 2, wn = warp & 3;
    int grp = lane >> 2, qd = lane & 3;

    const float* Ab = A + (size_t)(blockIdx.y * 128) * K;
    const float* Wb = W + (size_t)(blockIdx.x * 128) * K;
    float acc[4][4][4] = {};
    cpa_loop(Ab, K, Wb, K, K / 16, As, Bs, acc, tid, wm, wn, grp, qd);

    int row0 = blockIdx.y * 128 + wm * 64;
    int col0 = blockIdx.x * 128 + wn * 32;
    #pragma unroll
    for (int mi = 0; mi < 4; mi++) {
        #pragma unroll
        for (int ni = 0; ni < 4; ni++) {
            int r  = row0 + mi * 16 + grp;
            int cc = col0 + ni * 8 + qd * 2;
            float b0 = bias[cc], b1 = bias[cc + 1];
            float v00 = acc[mi][ni][0] + b0, v01 = acc[mi][ni][1] + b1;
            float v10 = acc[mi][ni][2] + b0, v11 = acc[mi][ni][3] + b1;
            if (round_out) {
                v00 = __uint_as_float(f2tf(v00)); v01 = __uint_as_float(f2tf(v01));
                v10 = __uint_as_float(f2tf(v10)); v11 = __uint_as_float(f2tf(v11));
            }
            *(float2*)(C + (size_t)r * N + cc)       = make_float2(v00, v01);
            *(float2*)(C + (size_t)(r + 8) * N + cc) = make_float2(v10, v11);
        }
    }
}

// ---------------------------------------------------------------------------
// Phase 1: stats only. QK tile MMA, per-row-tile (max, sumexp). NO e write.
// ---------------------------------------------------------------------------
#define QPAD 68
#define SC_SMEM (2 * 128 * QPAD * 4)   // 69632

__global__ __launch_bounds__(256, 2) void attn_stats()
{
    extern __shared__ float sm[];
    float (*Qs)[QPAD] = (float (*)[QPAD])sm;
    float (*Ks)[QPAD] = (float (*)[QPAD])(sm + 128 * QPAD);
    float (*rstat)[4] = (float (*)[4])sm;   // reuse after mainloop

    int tid = threadIdx.x;
    int warp = tid >> 5, lane = tid & 31;
    int wm = warp >> 2, wn = warp & 3;
    int grp = lane >> 2, qd = lane & 3;
    int bh = blockIdx.z, b = bh >> 4, h = bh & 15;

    const float* qb = g_q + (size_t)b * SEQ * DIM + (size_t)(blockIdx.y * 128) * DIM + h * DK;
    const float* kb = g_k + (size_t)b * SEQ * DIM + (size_t)(blockIdx.x * 128) * DIM + h * DK;

    #pragma unroll
    for (int i = 0; i < 8; i++) {
        int id = tid + i * 256;
        int r  = id >> 4;
        int c4 = (id & 15) << 2;
        cpa16(&Qs[r][c4], qb + (size_t)r * DIM + c4);
    }
    #pragma unroll
    for (int i = 0; i < 8; i++) {
        int id = tid + i * 256;
        int r  = id >> 4;
        int c4 = (id & 15) << 2;
        cpa16(&Ks[r][c4], kb + (size_t)r * DIM + c4);
    }
    CPA_COMMIT();
    CPA_WAIT0();
    __syncthreads();

    float acc[4][4][4] = {};
    #pragma unroll
    for (int kk8 = 0; kk8 < 64; kk8 += 8) {
        unsigned a[4][4], bf[4][2];
        #pragma unroll
        for (int mi = 0; mi < 4; mi++) {
            int m = wm * 64 + mi * 16;
            a[mi][0] = __float_as_uint(Qs[m + grp    ][kk8 + qd    ]);
            a[mi][1] = __float_as_uint(Qs[m + grp + 8][kk8 + qd    ]);
            a[mi][2] = __float_as_uint(Qs[m + grp    ][kk8 + qd + 4]);
            a[mi][3] = __float_as_uint(Qs[m + grp + 8][kk8 + qd + 4]);
        }
        #pragma unroll
        for (int ni = 0; ni < 4; ni++) {
            int n = wn * 32 + ni * 8 + grp;
            bf[ni][0] = __float_as_uint(Ks[n][kk8 + qd    ]);
            bf[ni][1] = __float_as_uint(Ks[n][kk8 + qd + 4]);
        }
        #pragma unroll
        for (int mi = 0; mi < 4; mi++)
            #pragma unroll
            for (int ni = 0; ni < 4; ni++)
                mma_tf32(acc[mi][ni], a[mi][0], a[mi][1], a[mi][2], a[mi][3],
                         bf[ni][0], bf[ni][1]);
    }
    __syncthreads();

    const float alpha = 0.125f;
    #pragma unroll
    for (int mi = 0; mi < 4; mi++)
        #pragma unroll
        for (int ni = 0; ni < 4; ni++)
            #pragma unroll
            for (int j = 0; j < 4; j++)
                acc[mi][ni][j] *= alpha;

    float msel[4][2];
    #pragma unroll
    for (int mi = 0; mi < 4; mi++) {
        float mA = -1e30f, mB = -1e30f;
        #pragma unroll
        for (int ni = 0; ni < 4; ni++) {
            mA = fmaxf(mA, fmaxf(acc[mi][ni][0], acc[mi][ni][1]));
            mB = fmaxf(mB, fmaxf(acc[mi][ni][2], acc[mi][ni][3]));
        }
        mA = fmaxf(mA, __shfl_xor_sync(0xffffffffu, mA, 1));
        mA = fmaxf(mA, __shfl_xor_sync(0xffffffffu, mA, 2));
        mB = fmaxf(mB, __shfl_xor_sync(0xffffffffu, mB, 1));
        mB = fmaxf(mB, __shfl_xor_sync(0xffffffffu, mB, 2));
        int rA = wm * 64 + mi * 16 + grp;
        if (qd == 0) { rstat[rA][wn] = mA; rstat[rA + 8][wn] = mB; }
    }
    __syncthreads();
    #pragma unroll
    for (int mi = 0; mi < 4; mi++) {
        int rA = wm * 64 + mi * 16 + grp;
        msel[mi][0] = fmaxf(fmaxf(rstat[rA][0],     rstat[rA][1]),
                            fmaxf(rstat[rA][2],     rstat[rA][3]));
        msel[mi][1] = fmaxf(fmaxf(rstat[rA + 8][0], rstat[rA + 8][1]),
                            fmaxf(rstat[rA + 8][2], rstat[rA + 8][3]));
    }
    __syncthreads();

    float ssel[4][2];
    #pragma unroll
    for (int mi = 0; mi < 4; mi++) {
        float sA = 0.f, sB = 0.f;
        #pragma unroll
        for (int ni = 0; ni < 4; ni++) {
            sA += __expf(acc[mi][ni][0] - msel[mi][0]);
            sA += __expf(acc[mi][ni][1] - msel[mi][0]);
            sB += __expf(acc[mi][ni][2] - msel[mi][1]);
            sB += __expf(acc[mi][ni][3] - msel[mi][1]);
        }
        sA += __shfl_xor_sync(0xffffffffu, sA, 1);
        sA += __shfl_xor_sync(0xffffffffu, sA, 2);
        sB += __shfl_xor_sync(0xffffffffu, sB, 1);
        sB += __shfl_xor_sync(0xffffffffu, sB, 2);
        int rA = wm * 64 + mi * 16 + grp;
        if (qd == 0) { rstat[rA][wn] = sA; rstat[rA + 8][wn] = sB; }
    }
    __syncthreads();
    #pragma unroll
    for (int mi = 0; mi < 4; mi++) {
        int rA = wm * 64 + mi * 16 + grp;
        ssel[mi][0] = (rstat[rA][0]     + rstat[rA][1])
                    + (rstat[rA][2]     + rstat[rA][3]);
        ssel[mi][1] = (rstat[rA + 8][0] + rstat[rA + 8][1])
                    + (rstat[rA + 8][2] + rstat[rA + 8][3]);
    }

    if (wn == 0 && qd == 0) {
        #pragma unroll
        for (int mi = 0; mi < 4; mi++) {
            #pragma unroll
            for (int half = 0; half < 2; half++) {
                int rowg = blockIdx.y * 128 + wm * 64 + mi * 16 + half * 8 + grp;
                size_t idx = ((size_t)(bh << 11) + rowg) * NCT + blockIdx.x;
                g_smax[idx] = msel[mi][half];
                g_ssum[idx] = ssel[mi][half];
            }
        }
    }
}

// ---------------------------------------------------------------------------
__global__ __launch_bounds__(256) void combine_stats()
{
    int gid = blockIdx.x * 256 + threadIdx.x;
    const float* mx = g_smax + (size_t)gid * NCT;
    const float* smv = g_ssum + (size_t)gid * NCT;
    float mv[NCT];
    float m = -1e30f;
    #pragma unroll
    for (int i = 0; i < NCT; i++) { mv[i] = mx[i]; m = fmaxf(m, mv[i]); }
    float s = 0.f;
    float ev[NCT];
    #pragma unroll
    for (int i = 0; i < NCT; i++) { ev[i] = __expf(mv[i] - m); s += smv[i] * ev[i]; }
    float inv = 1.0f / s;
    #pragma unroll
    for (int i = 0; i < NCT; i++) g_factor[(size_t)gid * NCT + i] = ev[i] * inv;
}

// ---------------------------------------------------------------------------
// Phase 2: recompute S in 32-row K-chunks, p = exp(s*a - m_t)*f_t, write final
// prob once + accumulate P@V. 256 threads, warps 2(M)x4(N). Q resident.
// Barrier schedule identical to the race-fixed R10 version.
// ---------------------------------------------------------------------------
#define CHK 32
#define PSP 36
#define OFF_QS 0                          // [128][68]
#define OFF_KS (OFF_QS + 128*68)          // [2][CHK][68]
#define OFF_VS (OFF_KS + 2*CHK*68)        // [2][CHK][72]
#define OFF_PS (OFF_VS + 2*CHK*72)        // [128][PSP]
#define F2_SMEM ((OFF_PS + 128*PSP) * 4)  // 89088 bytes

__global__ __launch_bounds__(256, 2) void attn_fused2(float* __restrict__ score)
{
    extern __shared__ float sm[];
    float    (*Qs)[68]      = (float (*)[68])(sm + OFF_QS);
    float    (*Ks)[CHK][68] = (float (*)[CHK][68])(sm + OFF_KS);
    unsigned (*Vs)[CHK][72] = (unsigned (*)[CHK][72])(sm + OFF_VS);
    unsigned (*Ps)[PSP]     = (unsigned (*)[PSP])(sm + OFF_PS);

    int tid = threadIdx.x;
    int warp = tid >> 5, lane = tid & 31;
    int wm = warp >> 2, wn = warp & 3;       // 2 x 4
    int grp = lane >> 2, qd = lane & 3;
    int bh = blockIdx.y, b = bh >> 4, h = bh & 15;
    int qt = blockIdx.x;

    const float* qb = g_q + (size_t)b * SEQ * DIM + (size_t)(qt * 128) * DIM + h * DK;
    const float* kb = g_k + (size_t)b * SEQ * DIM + h * DK;
    const float* vb = g_v + (size_t)b * SEQ * DIM + h * DK;
    float* ob = score + (size_t)bh * SEQ * SEQ + (size_t)(qt * 128) * SEQ;

    // preload Q tile (128x64) + K/V chunk 0 (32x64 each)
    #pragma unroll
    for (int i = 0; i < 8; i++) {
        int id = tid + i * 256;
        int r  = id >> 4;
        int c4 = (id & 15) << 2;
        cpa16(&Qs[r][c4], qb + (size_t)r * DIM + c4);
    }
    #pragma unroll
    for (int i = 0; i < 2; i++) {
        int id = tid + i * 256;       // 0..511
        int r  = id >> 4;             // 0..31
        int c4 = (id & 15) << 2;
        cpa16(&Ks[0][r][c4], kb + (size_t)r * DIM + c4);
        cpa16(&Vs[0][r][c4], vb + (size_t)r * DIM + c4);
    }
    CPA_COMMIT();
    CPA_WAIT0();
    __syncthreads();

    float acc[4][2][4] = {};
    float m_r[4][2], f_r[4][2];
    int buf = 0;
    const float alpha = 0.125f;
    const int NTCH = SEQ / CHK;   // 64

    for (int t = 0; t < NTCH; t++) {
        // prefetch next chunk (safe: end-of-prev-iteration barrier)
        if (t + 1 < NTCH) {
            int nb = buf ^ 1;
            #pragma unroll
            for (int i = 0; i < 2; i++) {
                int id = tid + i * 256;
                int r  = id >> 4;
                int c4 = (id & 15) << 2;
                cpa16(&Ks[nb][r][c4], kb + (size_t)((t + 1) * CHK + r) * DIM + c4);
                cpa16(&Vs[nb][r][c4], vb + (size_t)((t + 1) * CHK + r) * DIM + c4);
            }
            CPA_COMMIT();
        }
        if ((t & 3) == 0) {
            int ct = t >> 2;
            #pragma unroll
            for (int mi = 0; mi < 4; mi++) {
                #pragma unroll
                for (int hf = 0; hf < 2; hf++) {
                    int row = qt * 128 + wm * 64 + mi * 16 + hf * 8 + grp;
                    size_t idx = ((size_t)(bh << 11) + row) * NCT + ct;
                    m_r[mi][hf] = g_smax[idx];
                    f_r[mi][hf] = g_factor[idx];
                }
            }
        }

        // QK: S chunk [128 x 32]; warp (wm,wn) covers rows wm*64+64, cols wn*8+8
        float sacc[4][4] = {};
        #pragma unroll
        for (int kk8 = 0; kk8 < 64; kk8 += 8) {
            unsigned a[4][4], bb[2];
            #pragma unroll
            for (int mi = 0; mi < 4; mi++) {
                int m = wm * 64 + mi * 16;
                a[mi][0] = __float_as_uint(Qs[m + grp    ][kk8 + qd    ]);
                a[mi][1] = __float_as_uint(Qs[m + grp + 8][kk8 + qd    ]);
                a[mi][2] = __float_as_uint(Qs[m + grp    ][kk8 + qd + 4]);
                a[mi][3] = __float_as_uint(Qs[m + grp + 8][kk8 + qd + 4]);
            }
            {
                int n = wn * 8 + grp;
                bb[0] = __float_as_uint(Ks[buf][n][kk8 + qd    ]);
                bb[1] = __float_as_uint(Ks[buf][n][kk8 + qd + 4]);
            }
            #pragma unroll
            for (int mi = 0; mi < 4; mi++)
                mma_tf32(sacc[mi], a[mi][0], a[mi][1], a[mi][2], a[mi][3],
                         bb[0], bb[1]);
        }

        // p = exp(s*alpha - m_t) * f_t
        float p[4][4];
        #pragma unroll
        for (int mi = 0; mi < 4; mi++) {
            float s0 = sacc[mi][0] * alpha, s1 = sacc[mi][1] * alpha;
            float s2 = sacc[mi][2] * alpha, s3 = sacc[mi][3] * alpha;
            p[mi][0] = __expf(s0 - m_r[mi][0]) * f_r[mi][0];
            p[mi][1] = __expf(s1 - m_r[mi][0]) * f_r[mi][0];
            p[mi][2] = __expf(s2 - m_r[mi][1]) * f_r[mi][1];
            p[mi][3] = __expf(s3 - m_r[mi][1]) * f_r[mi][1];
        }

        // write final prob + stash tf32 bits in Ps (safe: end-of-prev barrier)
        int colL = wn * 8 + qd * 2;
        #pragma unroll
        for (int mi = 0; mi < 4; mi++) {
            int r0 = wm * 64 + mi * 16 + grp;
            *(float2*)(ob + (size_t)r0 * SEQ + t * CHK + colL) =
                make_float2(p[mi][0], p[mi][1]);
            *(float2*)(ob + (size_t)(r0 + 8) * SEQ + t * CHK + colL) =
                make_float2(p[mi][2], p[mi][3]);
            uint2 u0 = make_uint2(f2tf(p[mi][0]), f2tf(p[mi][1]));
            uint2 u1 = make_uint2(f2tf(p[mi][2]), f2tf(p[mi][3]));
            *(uint2*)&Ps[r0][colL]     = u0;
            *(uint2*)&Ps[r0 + 8][colL] = u1;
        }
        if (t + 1 < NTCH) CPA_WAIT0();
        __syncthreads();   // Ps visible; next K/V chunk landed

        // PV: acc += P_chunk[128x32] @ V_chunk[32x64]; warp tile 64x16
        #pragma unroll
        for (int kk = 0; kk < CHK; kk += 8) {
            unsigned a[4][4], bf[2][2];
            #pragma unroll
            for (int mi = 0; mi < 4; mi++) {
                int m = wm * 64 + mi * 16;
                a[mi][0] = Ps[m + grp    ][kk + qd    ];
                a[mi][1] = Ps[m + grp + 8][kk + qd    ];
                a[mi][2] = Ps[m + grp    ][kk + qd + 4];
                a[mi][3] = Ps[m + grp + 8][kk + qd + 4];
            }
            #pragma unroll
            for (int ni = 0; ni < 2; ni++) {
                int n = wn * 16 + ni * 8 + grp;
                bf[ni][0] = Vs[buf][kk + qd    ][n];
                bf[ni][1] = Vs[buf][kk + qd + 4][n];
            }
            #pragma unroll
            for (int mi = 0; mi < 4; mi++)
                #pragma unroll
                for (int ni = 0; ni < 2; ni++)
                    mma_tf32(acc[mi][ni], a[mi][0], a[mi][1], a[mi][2], a[mi][3],
                             bf[ni][0], bf[ni][1]);
        }
        __syncthreads();   // all reads of Ks/Vs[buf]/Ps done before next prefetch
        buf ^= 1;
    }

    // epilogue: write blended ROUNDED to tf32 bits (bit-identical to the cvt
    // the out-proj GEMM would otherwise do in-loop).
    float* obl = g_bl + (size_t)b * SEQ * DIM;
    int r0 = qt * 128 + wm * 64;
    int c0 = h * DK + wn * 16;
    #pragma unroll
    for (int mi = 0; mi < 4; mi++) {
        #pragma unroll
        for (int ni = 0; ni < 2; ni++) {
            int r  = r0 + mi * 16 + grp;
            int cc = c0 + ni * 8 + qd * 2;
            float2 o0 = make_float2(__uint_as_float(f2tf(acc[mi][ni][0])),
                                    __uint_as_float(f2tf(acc[mi][ni][1])));
            float2 o1 = make_float2(__uint_as_float(f2tf(acc[mi][ni][2])),
                                    __uint_as_float(f2tf(acc[mi][ni][3])));
            *(float2*)(obl + (size_t)r * DIM + cc)       = o0;
            *(float2*)(obl + (size_t)(r + 8) * DIM + cc) = o1;
        }
    }
}

// ---------------------------------------------------------------------------
extern "C" void kernel_launch(void* const* d_in, const int* in_sizes, int n_in,
                              void* d_out, int out_size)
{
    const float* query = (const float*)d_in[0];
    const float* key   = (const float*)d_in[1];
    const float* value = (const float*)d_in[2];
    const float* Wq    = (const float*)d_in[3];
    const float* bq    = (const float*)d_in[4];
    const float* Wk    = (const float*)d_in[5];
    const float* bk    = (const float*)d_in[6];
    const float* Wv    = (const float*)d_in[7];
    const float* bv    = (const float*)d_in[8];
    const float* Wo    = (const float*)d_in[9];
    const float* bo    = (const float*)d_in[10];

    float* out   = (float*)d_out;                          // [B,S,D]
    float* score = out + (size_t)BSZ * SEQ * DIM;          // [B,H,S,S]

    float *pq, *pk, *pv, *pbl, *prq, *prk, *prv, *pw;
    cudaGetSymbolAddress((void**)&pq,  g_q);
    cudaGetSymbolAddress((void**)&pk,  g_k);
    cudaGetSymbolAddress((void**)&pv,  g_v);
    cudaGetSymbolAddress((void**)&pbl, g_bl);
    cudaGetSymbolAddress((void**)&prq, g_rq);
    cudaGetSymbolAddress((void**)&prk, g_rk);
    cudaGetSymbolAddress((void**)&prv, g_rv);
    cudaGetSymbolAddress((void**)&pw,  g_w);

    cudaFuncSetAttribute(gemm_cpa,
        cudaFuncAttributeMaxDynamicSharedMemorySize, GEMM_SMEM);
    cudaFuncSetAttribute(attn_stats,
        cudaFuncAttributeMaxDynamicSharedMemorySize, SC_SMEM);
    cudaFuncSetAttribute(attn_fused2,
        cudaFuncAttributeMaxDynamicSharedMemorySize, F2_SMEM);

    // pre-round inputs + weights to tf32 bits
    round3<<<dim3(MTOT * DIM / 4 / 256, 3), 256>>>(query, key, value, prq, prk, prv);
    round4<<<dim3(DIM * DIM / 4 / 256, 4), 256>>>(Wq, Wk, Wv, Wo, pw);

    dim3 gp(DIM / 128, MTOT / 128);   // (8, 32)
    gemm_cpa<<<gp, 256, GEMM_SMEM>>>(prq, pw,                 bq, pq, MTOT, DIM, DIM, 1);
    gemm_cpa<<<gp, 256, GEMM_SMEM>>>(prk, pw + DIM * DIM,     bk, pk, MTOT, DIM, DIM, 1);
    gemm_cpa<<<gp, 256, GEMM_SMEM>>>(prv, pw + 2 * DIM * DIM, bv, pv, MTOT, DIM, DIM, 1);

    attn_stats<<<dim3(SEQ / 128, SEQ / 128, BH), 256, SC_SMEM>>>();
    combine_stats<<<NROWS / 256, 256>>>();
    attn_fused2<<<dim3(SEQ / 128, BH), 256, F2_SMEM>>>(score);

    gemm_cpa<<<gp, 256, GEMM_SMEM>>>(pbl, pw + 3 * DIM * DIM, bo, out, MTOT, DIM, DIM, 0);
}

// round 12
// speedup vs baseline: 1.0177x; 1.0177x over previous
#include <cuda_runtime.h>
#include <math.h>
#include <stdint.h>

#define BSZ 2
#define SEQ 2048
#define DIM 1024
#define NH  16
#define DK  64
#define BH  (BSZ*NH)   // 32
#define MTOT (BSZ*SEQ) // 4096
#define NROWS (BH*SEQ) // 65536
#define NCT  16        // col tiles of 128 per row

// Scratch (allocation-free rule: __device__ globals)
__device__ float g_q [BSZ*SEQ*DIM];
__device__ float g_k [BSZ*SEQ*DIM];
__device__ float g_v [BSZ*SEQ*DIM];
__device__ float g_bl[BSZ*SEQ*DIM];
__device__ float g_rq[BSZ*SEQ*DIM];     // tf32-rounded inputs
__device__ float g_rk[BSZ*SEQ*DIM];
__device__ float g_rv[BSZ*SEQ*DIM];
__device__ float g_w [4*DIM*DIM];       // tf32-rounded weights
__device__ float g_smax  [NROWS*NCT];
__device__ float g_ssum  [NROWS*NCT];
__device__ float g_factor[NROWS*NCT];

// ---------------------------------------------------------------------------
// helpers
// ---------------------------------------------------------------------------
__device__ __forceinline__ unsigned f2tf(float x) {
    unsigned r;
    asm("cvt.rna.tf32.f32 %0, %1;" : "=r"(r) : "f"(x));
    return r;
}

__device__ __forceinline__ void mma_tf32(float c[4],
    unsigned a0, unsigned a1, unsigned a2, unsigned a3,
    unsigned b0, unsigned b1)
{
    asm volatile(
        "mma.sync.aligned.m16n8k8.row.col.f32.tf32.tf32.f32 "
        "{%0,%1,%2,%3}, {%4,%5,%6,%7}, {%8,%9}, {%0,%1,%2,%3};\n"
        : "+f"(c[0]), "+f"(c[1]), "+f"(c[2]), "+f"(c[3])
        : "r"(a0), "r"(a1), "r"(a2), "r"(a3), "r"(b0), "r"(b1));
}

__device__ __forceinline__ unsigned smem_u32(const void* p) {
    unsigned a;
    asm("{ .reg .u64 t; cvta.to.shared.u64 t, %1; cvt.u32.u64 %0, t; }"
        : "=r"(a) : "l"(p));
    return a;
}

#define CPA_COMMIT() asm volatile("cp.async.commit_group;" ::: "memory")
#define CPA_WAIT1()  asm volatile("cp.async.wait_group 1;" ::: "memory")
#define CPA_WAIT0()  asm volatile("cp.async.wait_group 0;" ::: "memory")

__device__ __forceinline__ void cpa16(const void* smem_dst, const float* gsrc) {
    unsigned sa = smem_u32(smem_dst);
    asm volatile("cp.async.cg.shared.global [%0], [%1], 16;"
                 :: "r"(sa), "l"(gsrc) : "memory");
}

// ---------------------------------------------------------------------------
// pre-round kernels (tf32 bits, idempotent w.r.t. later MMA use)
// ---------------------------------------------------------------------------
__global__ __launch_bounds__(256) void round3(
    const float* __restrict__ a, const float* __restrict__ b,
    const float* __restrict__ c,
    float* __restrict__ da, float* __restrict__ db, float* __restrict__ dc)
{
    const float* s; float* d;
    if      (blockIdx.y == 0) { s = a; d = da; }
    else if (blockIdx.y == 1) { s = b; d = db; }
    else                      { s = c; d = dc; }
    int i = blockIdx.x * 256 + threadIdx.x;
    float4 v = ((const float4*)s)[i];
    uint4 o = make_uint4(f2tf(v.x), f2tf(v.y), f2tf(v.z), f2tf(v.w));
    ((uint4*)d)[i] = o;
}

__global__ __launch_bounds__(256) void round4(
    const float* __restrict__ a, const float* __restrict__ b,
    const float* __restrict__ c, const float* __restrict__ d,
    float* __restrict__ dst)
{
    const float* s;
    if      (blockIdx.y == 0) s = a;
    else if (blockIdx.y == 1) s = b;
    else if (blockIdx.y == 2) s = c;
    else                      s = d;
    int i = blockIdx.x * 256 + threadIdx.x;
    float4 v = ((const float4*)s)[i];
    uint4 o = make_uint4(f2tf(v.x), f2tf(v.y), f2tf(v.z), f2tf(v.w));
    ((uint4*)(dst + (size_t)blockIdx.y * DIM * DIM))[i] = o;
}

// ---------------------------------------------------------------------------
#define TPAD 20   // floats per padded row in GEMM tiles

__device__ __forceinline__ void cpa_tile(
    float (*dst)[TPAD], const float* __restrict__ src, int lda, int tid)
{
    #pragma unroll
    for (int i = 0; i < 2; i++) {
        int id = tid + i * 256;       // 0..511
        int r  = id >> 2;             // 0..127
        int c4 = (id & 3) << 2;       // 0,4,8,12
        cpa16(&dst[r][c4], src + (size_t)r * lda + c4);
    }
}

// One 16-K tile of MMAs; inputs are PRE-ROUNDED tf32 bits (no cvt).
__device__ __forceinline__ void tile_mma(
    const float (*As)[TPAD], const float (*Bs)[TPAD],
    float acc[4][4][4], int wm, int wn, int grp, int qd)
{
    #pragma unroll
    for (int kk = 0; kk < 16; kk += 8) {
        unsigned a[4][4], b[4][2];
        #pragma unroll
        for (int mi = 0; mi < 4; mi++) {
            int m = wm * 64 + mi * 16;
            a[mi][0] = __float_as_uint(As[m + grp    ][kk + qd    ]);
            a[mi][1] = __float_as_uint(As[m + grp + 8][kk + qd    ]);
            a[mi][2] = __float_as_uint(As[m + grp    ][kk + qd + 4]);
            a[mi][3] = __float_as_uint(As[m + grp + 8][kk + qd + 4]);
        }
        #pragma unroll
        for (int ni = 0; ni < 4; ni++) {
            int n = wn * 32 + ni * 8 + grp;
            b[ni][0] = __float_as_uint(Bs[n][kk + qd    ]);
            b[ni][1] = __float_as_uint(Bs[n][kk + qd + 4]);
        }
        #pragma unroll
        for (int mi = 0; mi < 4; mi++)
            #pragma unroll
            for (int ni = 0; ni < 4; ni++)
                mma_tf32(acc[mi][ni], a[mi][0], a[mi][1], a[mi][2], a[mi][3],
                         b[ni][0], b[ni][1]);
    }
}

// 3-stage cp.async mainloop over nk 16-K tiles (nk >= 3).
__device__ __forceinline__ void cpa_loop(
    const float* __restrict__ A, int lda,
    const float* __restrict__ B, int ldb, int nk,
    float (*As)[128][TPAD], float (*Bs)[128][TPAD],
    float acc[4][4][4], int tid, int wm, int wn, int grp, int qd)
{
    cpa_tile(As[0], A, lda, tid);
    cpa_tile(Bs[0], B, ldb, tid);
    CPA_COMMIT();
    cpa_tile(As[1], A + 16, lda, tid);
    cpa_tile(Bs[1], B + 16, ldb, tid);
    CPA_COMMIT();

    int cur = 0;
    for (int t = 0; t < nk; t++) {
        if (t < nk - 1) CPA_WAIT1(); else CPA_WAIT0();
        __syncthreads();
        tile_mma(As[cur], Bs[cur], acc, wm, wn, grp, qd);
        if (t + 2 < nk) {
            int nxt = cur + 2; if (nxt >= 3) nxt -= 3;
            cpa_tile(As[nxt], A + (t + 2) * 16, lda, tid);
            cpa_tile(Bs[nxt], B + (t + 2) * 16, ldb, tid);
            CPA_COMMIT();
        }
        if (++cur == 3) cur = 0;
    }
}

#define GEMM_SMEM (3 * 128 * TPAD * 4 * 2)          // 61440

// ---------------------------------------------------------------------------
// GEMM: C[M,N] = A[M,K] @ W[N,K]^T + bias[N]; A,W pre-rounded tf32 bits.
// ---------------------------------------------------------------------------
__global__ __launch_bounds__(256, 2) void gemm_cpa(
    const float* __restrict__ A, const float* __restrict__ W,
    const float* __restrict__ bias, float* __restrict__ C,
    int M, int N, int K, int round_out)
{
    extern __shared__ float sm[];
    float (*As)[128][TPAD] = (float (*)[128][TPAD])sm;
    float (*Bs)[128][TPAD] = (float (*)[128][TPAD])(sm + 3 * 128 * TPAD);

    int tid = threadIdx.x;
    int warp = tid >> 5, lane = tid & 31;
    int wm = warp >> 2, wn = warp & 3;
    int grp = lane >> 2, qd = lane & 3;

    const float* Ab = A + (size_t)(blockIdx.y * 128) * K;
    const float* Wb = W + (size_t)(blockIdx.x * 128) * K;
    float acc[4][4][4] = {};
    cpa_loop(Ab, K, Wb, K, K / 16, As, Bs, acc, tid, wm, wn, grp, qd);

    int row0 = blockIdx.y * 128 + wm * 64;
    int col0 = blockIdx.x * 128 + wn * 32;
    #pragma unroll
    for (int mi = 0; mi < 4; mi++) {
        #pragma unroll
        for (int ni = 0; ni < 4; ni++) {
            int r  = row0 + mi * 16 + grp;
            int cc = col0 + ni * 8 + qd * 2;
            float b0 = bias[cc], b1 = bias[cc + 1];
            float v00 = acc[mi][ni][0] + b0, v01 = acc[mi][ni][1] + b1;
            float v10 = acc[mi][ni][2] + b0, v11 = acc[mi][ni][3] + b1;
            if (round_out) {
                v00 = __uint_as_float(f2tf(v00)); v01 = __uint_as_float(f2tf(v01));
                v10 = __uint_as_float(f2tf(v10)); v11 = __uint_as_float(f2tf(v11));
            }
            *(float2*)(C + (size_t)r * N + cc)       = make_float2(v00, v01);
            *(float2*)(C + (size_t)(r + 8) * N + cc) = make_float2(v10, v11);
        }
    }
}

// ---------------------------------------------------------------------------
// scores: Q,K tiles fully resident (K=64), inputs pre-rounded (no cvt).
// Writes e = exp(x/8 - m_tile) + per-row-tile (max,sum) partials.
// ---------------------------------------------------------------------------
#define QPAD 68
#define SC_SMEM (2 * 128 * QPAD * 4)   // 69632

__global__ __launch_bounds__(256, 2) void attn_scores_v3(float* __restrict__ score)
{
    extern __shared__ float sm[];
    float (*Qs)[QPAD] = (float (*)[QPAD])sm;
    float (*Ks)[QPAD] = (float (*)[QPAD])(sm + 128 * QPAD);
    float (*rstat)[4] = (float (*)[4])sm;   // reuse after mainloop

    int tid = threadIdx.x;
    int warp = tid >> 5, lane = tid & 31;
    int wm = warp >> 2, wn = warp & 3;
    int grp = lane >> 2, qd = lane & 3;
    int bh = blockIdx.z, b = bh >> 4, h = bh & 15;

    const float* qb = g_q + (size_t)b * SEQ * DIM + (size_t)(blockIdx.y * 128) * DIM + h * DK;
    const float* kb = g_k + (size_t)b * SEQ * DIM + (size_t)(blockIdx.x * 128) * DIM + h * DK;

    #pragma unroll
    for (int i = 0; i < 8; i++) {
        int id = tid + i * 256;       // 0..2047
        int r  = id >> 4;             // 0..127
        int c4 = (id & 15) << 2;      // 0..60
        cpa16(&Qs[r][c4], qb + (size_t)r * DIM + c4);
    }
    #pragma unroll
    for (int i = 0; i < 8; i++) {
        int id = tid + i * 256;
        int r  = id >> 4;
        int c4 = (id & 15) << 2;
        cpa16(&Ks[r][c4], kb + (size_t)r * DIM + c4);
    }
    CPA_COMMIT();
    CPA_WAIT0();
    __syncthreads();

    float acc[4][4][4] = {};
    #pragma unroll
    for (int kk8 = 0; kk8 < 64; kk8 += 8) {
        unsigned a[4][4], bf[4][2];
        #pragma unroll
        for (int mi = 0; mi < 4; mi++) {
            int m = wm * 64 + mi * 16;
            a[mi][0] = __float_as_uint(Qs[m + grp    ][kk8 + qd    ]);
            a[mi][1] = __float_as_uint(Qs[m + grp + 8][kk8 + qd    ]);
            a[mi][2] = __float_as_uint(Qs[m + grp    ][kk8 + qd + 4]);
            a[mi][3] = __float_as_uint(Qs[m + grp + 8][kk8 + qd + 4]);
        }
        #pragma unroll
        for (int ni = 0; ni < 4; ni++) {
            int n = wn * 32 + ni * 8 + grp;
            bf[ni][0] = __float_as_uint(Ks[n][kk8 + qd    ]);
            bf[ni][1] = __float_as_uint(Ks[n][kk8 + qd + 4]);
        }
        #pragma unroll
        for (int mi = 0; mi < 4; mi++)
            #pragma unroll
            for (int ni = 0; ni < 4; ni++)
                mma_tf32(acc[mi][ni], a[mi][0], a[mi][1], a[mi][2], a[mi][3],
                         bf[ni][0], bf[ni][1]);
    }
    __syncthreads();   // tiles dead; rstat aliases smem

    const float alpha = 0.125f;
    #pragma unroll
    for (int mi = 0; mi < 4; mi++)
        #pragma unroll
        for (int ni = 0; ni < 4; ni++)
            #pragma unroll
            for (int j = 0; j < 4; j++)
                acc[mi][ni][j] *= alpha;

    float msel[4][2];
    #pragma unroll
    for (int mi = 0; mi < 4; mi++) {
        float mA = -1e30f, mB = -1e30f;
        #pragma unroll
        for (int ni = 0; ni < 4; ni++) {
            mA = fmaxf(mA, fmaxf(acc[mi][ni][0], acc[mi][ni][1]));
            mB = fmaxf(mB, fmaxf(acc[mi][ni][2], acc[mi][ni][3]));
        }
        mA = fmaxf(mA, __shfl_xor_sync(0xffffffffu, mA, 1));
        mA = fmaxf(mA, __shfl_xor_sync(0xffffffffu, mA, 2));
        mB = fmaxf(mB, __shfl_xor_sync(0xffffffffu, mB, 1));
        mB = fmaxf(mB, __shfl_xor_sync(0xffffffffu, mB, 2));
        int rA = wm * 64 + mi * 16 + grp;
        if (qd == 0) { rstat[rA][wn] = mA; rstat[rA + 8][wn] = mB; }
    }
    __syncthreads();
    #pragma unroll
    for (int mi = 0; mi < 4; mi++) {
        int rA = wm * 64 + mi * 16 + grp;
        msel[mi][0] = fmaxf(fmaxf(rstat[rA][0],     rstat[rA][1]),
                            fmaxf(rstat[rA][2],     rstat[rA][3]));
        msel[mi][1] = fmaxf(fmaxf(rstat[rA + 8][0], rstat[rA + 8][1]),
                            fmaxf(rstat[rA + 8][2], rstat[rA + 8][3]));
    }
    __syncthreads();

    float ssel[4][2];
    #pragma unroll
    for (int mi = 0; mi < 4; mi++) {
        float sA = 0.f, sB = 0.f;
        #pragma unroll
        for (int ni = 0; ni < 4; ni++) {
            acc[mi][ni][0] = __expf(acc[mi][ni][0] - msel[mi][0]);
            acc[mi][ni][1] = __expf(acc[mi][ni][1] - msel[mi][0]);
            acc[mi][ni][2] = __expf(acc[mi][ni][2] - msel[mi][1]);
            acc[mi][ni][3] = __expf(acc[mi][ni][3] - msel[mi][1]);
            sA += acc[mi][ni][0] + acc[mi][ni][1];
            sB += acc[mi][ni][2] + acc[mi][ni][3];
        }
        sA += __shfl_xor_sync(0xffffffffu, sA, 1);
        sA += __shfl_xor_sync(0xffffffffu, sA, 2);
        sB += __shfl_xor_sync(0xffffffffu, sB, 1);
        sB += __shfl_xor_sync(0xffffffffu, sB, 2);
        int rA = wm * 64 + mi * 16 + grp;
        if (qd == 0) { rstat[rA][wn] = sA; rstat[rA + 8][wn] = sB; }
    }
    __syncthreads();
    #pragma unroll
    for (int mi = 0; mi < 4; mi++) {
        int rA = wm * 64 + mi * 16 + grp;
        ssel[mi][0] = (rstat[rA][0]     + rstat[rA][1])
                    + (rstat[rA][2]     + rstat[rA][3]);
        ssel[mi][1] = (rstat[rA + 8][0] + rstat[rA + 8][1])
                    + (rstat[rA + 8][2] + rstat[rA + 8][3]);
    }

    float* ob = score + (size_t)bh * SEQ * SEQ;
    int row0 = blockIdx.y * 128 + wm * 64;
    int col0 = blockIdx.x * 128 + wn * 32;
    #pragma unroll
    for (int mi = 0; mi < 4; mi++) {
        #pragma unroll
        for (int ni = 0; ni < 4; ni++) {
            int r  = row0 + mi * 16 + grp;
            int cc = col0 + ni * 8 + qd * 2;
            *(float2*)(ob + (size_t)r * SEQ + cc) =
                make_float2(acc[mi][ni][0], acc[mi][ni][1]);
            *(float2*)(ob + (size_t)(r + 8) * SEQ + cc) =
                make_float2(acc[mi][ni][2], acc[mi][ni][3]);
        }
    }

    if (wn == 0 && qd == 0) {
        #pragma unroll
        for (int mi = 0; mi < 4; mi++) {
            #pragma unroll
            for (int half = 0; half < 2; half++) {
                int rowg = blockIdx.y * 128 + wm * 64 + mi * 16 + half * 8 + grp;
                size_t idx = ((size_t)(bh << 11) + rowg) * NCT + blockIdx.x;
                g_smax[idx] = msel[mi][half];
                g_ssum[idx] = ssel[mi][half];
            }
        }
    }
}

// ---------------------------------------------------------------------------
__global__ __launch_bounds__(256) void combine_stats()
{
    int gid = blockIdx.x * 256 + threadIdx.x;
    const float* mx = g_smax + (size_t)gid * NCT;
    const float* smv = g_ssum + (size_t)gid * NCT;
    float mv[NCT];
    float m = -1e30f;
    #pragma unroll
    for (int i = 0; i < NCT; i++) { mv[i] = mx[i]; m = fmaxf(m, mv[i]); }
    float s = 0.f;
    float ev[NCT];
    #pragma unroll
    for (int i = 0; i < NCT; i++) { ev[i] = __expf(mv[i] - m); s += smv[i] * ev[i]; }
    float inv = 1.0f / s;
    #pragma unroll
    for (int i = 0; i < NCT; i++) g_factor[(size_t)gid * NCT + i] = ev[i] * inv;
}

// ---------------------------------------------------------------------------
// PV fused: p = e*factor written in place (final probs), blended = P @ V,
// blended stored tf32-rounded (bit-identical to out-proj's former in-loop cvt).
// 128 threads, warps 2x2, warp tile 64x32. V pre-rounded (no cvt at STS).
// ---------------------------------------------------------------------------
__global__ __launch_bounds__(128, 2) void attn_pv_fused(float* __restrict__ score)
{
    __shared__ unsigned Ps[2][16][136];
    __shared__ unsigned Vs[2][16][72];
    int tid = threadIdx.x;
    int bh = blockIdx.y, b = bh >> 4, h = bh & 15;
    int row0 = blockIdx.x * 128;
    float* pb = score + (size_t)bh * SEQ * SEQ + (size_t)row0 * SEQ;
    const float* vb = g_v + (size_t)b * SEQ * DIM + h * DK;
    const float* fb = g_factor + ((size_t)(bh << 11) + row0) * NCT;

    int warp = tid >> 5, lane = tid & 31;
    int wm = warp >> 1, wn = warp & 1;
    int grp = lane >> 2, qd = lane & 3;
    float acc[4][4][4] = {};

    float4 pe[4]; float pf[4]; float4 pvv[2];

    #pragma unroll
    for (int i = 0; i < 4; i++) {
        int id = tid + i * 128;
        int r  = id >> 2;
        int c  = (id & 3) << 2;
        pe[i] = *(const float4*)(pb + (size_t)r * SEQ + c);
        pf[i] = fb[r * NCT + 0];
    }
    #pragma unroll
    for (int i = 0; i < 2; i++) {
        int id = tid + i * 128;
        int r = id >> 4, c = (id & 15) << 2;
        pvv[i] = *(const float4*)(vb + (size_t)r * DIM + c);
    }
    #pragma unroll
    for (int i = 0; i < 4; i++) {
        int id = tid + i * 128;
        int r  = id >> 2;
        int c  = (id & 3) << 2;
        float4 p = make_float4(pe[i].x * pf[i], pe[i].y * pf[i],
                               pe[i].z * pf[i], pe[i].w * pf[i]);
        *(float4*)(pb + (size_t)r * SEQ + c) = p;
        Ps[0][c+0][r] = f2tf(p.x); Ps[0][c+1][r] = f2tf(p.y);
        Ps[0][c+2][r] = f2tf(p.z); Ps[0][c+3][r] = f2tf(p.w);
    }
    #pragma unroll
    for (int i = 0; i < 2; i++) {
        int id = tid + i * 128;
        int r = id >> 4, c = (id & 15) << 2;
        Vs[0][r][c+0] = __float_as_uint(pvv[i].x); Vs[0][r][c+1] = __float_as_uint(pvv[i].y);
        Vs[0][r][c+2] = __float_as_uint(pvv[i].z); Vs[0][r][c+3] = __float_as_uint(pvv[i].w);
    }
    __syncthreads();

    const int NK = SEQ / 16;
    for (int t = 0; t < NK; t++) {
        int cur = t & 1;
        if (t + 1 < NK) {
            int ct = (t + 1) >> 3;
            #pragma unroll
            for (int i = 0; i < 4; i++) {
                int id = tid + i * 128;
                int r  = id >> 2;
                int c  = (id & 3) << 2;
                pe[i] = *(const float4*)(pb + (size_t)r * SEQ + (t + 1) * 16 + c);
                pf[i] = fb[r * NCT + ct];
            }
            #pragma unroll
            for (int i = 0; i < 2; i++) {
                int id = tid + i * 128;
                int r = id >> 4, c = (id & 15) << 2;
                pvv[i] = *(const float4*)(vb + (size_t)((t + 1) * 16 + r) * DIM + c);
            }
        }
        #pragma unroll
        for (int kk = 0; kk < 16; kk += 8) {
            unsigned a[4][4], bf[4][2];
            #pragma unroll
            for (int mi = 0; mi < 4; mi++) {
                int m = wm * 64 + mi * 16;
                a[mi][0] = Ps[cur][kk + qd    ][m + grp    ];
                a[mi][1] = Ps[cur][kk + qd    ][m + grp + 8];
                a[mi][2] = Ps[cur][kk + qd + 4][m + grp    ];
                a[mi][3] = Ps[cur][kk + qd + 4][m + grp + 8];
            }
            #pragma unroll
            for (int ni = 0; ni < 4; ni++) {
                int n = wn * 32 + ni * 8 + grp;
                bf[ni][0] = Vs[cur][kk + qd    ][n];
                bf[ni][1] = Vs[cur][kk + qd + 4][n];
            }
            #pragma unroll
            for (int mi = 0; mi < 4; mi++)
                #pragma unroll
                for (int ni = 0; ni < 4; ni++)
                    mma_tf32(acc[mi][ni], a[mi][0], a[mi][1], a[mi][2], a[mi][3],
                             bf[ni][0], bf[ni][1]);
        }
        if (t + 1 < NK) {
            int nxt = cur ^ 1;
            #pragma unroll
            for (int i = 0; i < 4; i++) {
                int id = tid + i * 128;
                int r  = id >> 2;
                int c  = (id & 3) << 2;
                float4 p = make_float4(pe[i].x * pf[i], pe[i].y * pf[i],
                                       pe[i].z * pf[i], pe[i].w * pf[i]);
                *(float4*)(pb + (size_t)r * SEQ + (t + 1) * 16 + c) = p;
                Ps[nxt][c+0][r] = f2tf(p.x); Ps[nxt][c+1][r] = f2tf(p.y);
                Ps[nxt][c+2][r] = f2tf(p.z); Ps[nxt][c+3][r] = f2tf(p.w);
            }
            #pragma unroll
            for (int i = 0; i < 2; i++) {
                int id = tid + i * 128;
                int r = id >> 4, c = (id & 15) << 2;
                Vs[nxt][r][c+0] = __float_as_uint(pvv[i].x); Vs[nxt][r][c+1] = __float_as_uint(pvv[i].y);
                Vs[nxt][r][c+2] = __float_as_uint(pvv[i].z); Vs[nxt][r][c+3] = __float_as_uint(pvv[i].w);
            }
            __syncthreads();
        }
    }

    // store blended pre-rounded to tf32 bits for the cvt-free out-proj GEMM
    float* ob = g_bl + (size_t)b * SEQ * DIM;
    int r0 = row0 + wm * 64;
    int c0 = h * DK + wn * 32;
    #pragma unroll
    for (int mi = 0; mi < 4; mi++) {
        #pragma unroll
        for (int ni = 0; ni < 4; ni++) {
            int r  = r0 + mi * 16 + grp;
            int cc = c0 + ni * 8 + qd * 2;
            float2 o0 = make_float2(__uint_as_float(f2tf(acc[mi][ni][0])),
                                    __uint_as_float(f2tf(acc[mi][ni][1])));
            float2 o1 = make_float2(__uint_as_float(f2tf(acc[mi][ni][2])),
                                    __uint_as_float(f2tf(acc[mi][ni][3])));
            *(float2*)(ob + (size_t)r * DIM + cc)       = o0;
            *(float2*)(ob + (size_t)(r + 8) * DIM + cc) = o1;
        }
    }
}

// ---------------------------------------------------------------------------
extern "C" void kernel_launch(void* const* d_in, const int* in_sizes, int n_in,
                              void* d_out, int out_size)
{
    const float* query = (const float*)d_in[0];
    const float* key   = (const float*)d_in[1];
    const float* value = (const float*)d_in[2];
    const float* Wq    = (const float*)d_in[3];
    const float* bq    = (const float*)d_in[4];
    const float* Wk    = (const float*)d_in[5];
    const float* bk    = (const float*)d_in[6];
    const float* Wv    = (const float*)d_in[7];
    const float* bv    = (const float*)d_in[8];
    const float* Wo    = (const float*)d_in[9];
    const float* bo    = (const float*)d_in[10];

    float* out   = (float*)d_out;                          // [B,S,D]
    float* score = out + (size_t)BSZ * SEQ * DIM;          // [B,H,S,S]

    float *pq, *pk, *pv, *pbl, *prq, *prk, *prv, *pw;
    cudaGetSymbolAddress((void**)&pq,  g_q);
    cudaGetSymbolAddress((void**)&pk,  g_k);
    cudaGetSymbolAddress((void**)&pv,  g_v);
    cudaGetSymbolAddress((void**)&pbl, g_bl);
    cudaGetSymbolAddress((void**)&prq, g_rq);
    cudaGetSymbolAddress((void**)&prk, g_rk);
    cudaGetSymbolAddress((void**)&prv, g_rv);
    cudaGetSymbolAddress((void**)&pw,  g_w);

    cudaFuncSetAttribute(gemm_cpa,
        cudaFuncAttributeMaxDynamicSharedMemorySize, GEMM_SMEM);
    cudaFuncSetAttribute(attn_scores_v3,
        cudaFuncAttributeMaxDynamicSharedMemorySize, SC_SMEM);

    // pre-round inputs + weights to tf32 bits
    round3<<<dim3(MTOT * DIM / 4 / 256, 3), 256>>>(query, key, value, prq, prk, prv);
    round4<<<dim3(DIM * DIM / 4 / 256, 4), 256>>>(Wq, Wk, Wv, Wo, pw);

    dim3 gp(DIM / 128, MTOT / 128);   // (8, 32)
    gemm_cpa<<<gp, 256, GEMM_SMEM>>>(prq, pw,                 bq, pq, MTOT, DIM, DIM, 1);
    gemm_cpa<<<gp, 256, GEMM_SMEM>>>(prk, pw + DIM * DIM,     bk, pk, MTOT, DIM, DIM, 1);
    gemm_cpa<<<gp, 256, GEMM_SMEM>>>(prv, pw + 2 * DIM * DIM, bv, pv, MTOT, DIM, DIM, 1);

    attn_scores_v3<<<dim3(SEQ / 128, SEQ / 128, BH), 256, SC_SMEM>>>(score);
    combine_stats<<<NROWS / 256, 256>>>();
    attn_pv_fused<<<dim3(SEQ / 128, BH), 128>>>(score);

    gemm_cpa<<<gp, 256, GEMM_SMEM>>>(pbl, pw + 3 * DIM * DIM, bo, out, MTOT, DIM, DIM, 0);
}

// round 13
// speedup vs baseline: 1.1487x; 1.1288x over previous
#include <cuda_runtime.h>
#include <math.h>
#include <stdint.h>

#define BSZ 2
#define SEQ 2048
#define DIM 1024
#define NH  16
#define DK  64
#define BH  (BSZ*NH)   // 32
#define MTOT (BSZ*SEQ) // 4096
#define NROWS (BH*SEQ) // 65536
#define NCT  16        // col tiles of 128 per row

// Scratch (allocation-free rule: __device__ globals)
__device__ float g_q [BSZ*SEQ*DIM];
__device__ float g_k [BSZ*SEQ*DIM];
__device__ float g_v [BSZ*SEQ*DIM];
__device__ float g_bl[BSZ*SEQ*DIM];
__device__ float g_rq[BSZ*SEQ*DIM];     // tf32-rounded inputs
__device__ float g_rk[BSZ*SEQ*DIM];
__device__ float g_rv[BSZ*SEQ*DIM];
__device__ float g_w [4*DIM*DIM];       // tf32-rounded weights
__device__ float g_smax  [NROWS*NCT];
__device__ float g_ssum  [NROWS*NCT];
__device__ float g_factor[NROWS*NCT];

// ---------------------------------------------------------------------------
// helpers
// ---------------------------------------------------------------------------
__device__ __forceinline__ unsigned f2tf(float x) {
    unsigned r;
    asm("cvt.rna.tf32.f32 %0, %1;" : "=r"(r) : "f"(x));
    return r;
}

__device__ __forceinline__ void mma_tf32(float c[4],
    unsigned a0, unsigned a1, unsigned a2, unsigned a3,
    unsigned b0, unsigned b1)
{
    asm volatile(
        "mma.sync.aligned.m16n8k8.row.col.f32.tf32.tf32.f32 "
        "{%0,%1,%2,%3}, {%4,%5,%6,%7}, {%8,%9}, {%0,%1,%2,%3};\n"
        : "+f"(c[0]), "+f"(c[1]), "+f"(c[2]), "+f"(c[3])
        : "r"(a0), "r"(a1), "r"(a2), "r"(a3), "r"(b0), "r"(b1));
}

__device__ __forceinline__ unsigned smem_u32(const void* p) {
    unsigned a;
    asm("{ .reg .u64 t; cvta.to.shared.u64 t, %1; cvt.u32.u64 %0, t; }"
        : "=r"(a) : "l"(p));
    return a;
}

#define CPA_COMMIT() asm volatile("cp.async.commit_group;" ::: "memory")
#define CPA_WAIT1()  asm volatile("cp.async.wait_group 1;" ::: "memory")
#define CPA_WAIT0()  asm volatile("cp.async.wait_group 0;" ::: "memory")

__device__ __forceinline__ void cpa16(const void* smem_dst, const float* gsrc) {
    unsigned sa = smem_u32(smem_dst);
    asm volatile("cp.async.cg.shared.global [%0], [%1], 16;"
                 :: "r"(sa), "l"(gsrc) : "memory");
}

// ---------------------------------------------------------------------------
// pre-round kernels (tf32 bits, idempotent w.r.t. later MMA use)
// ---------------------------------------------------------------------------
__global__ __launch_bounds__(256) void round3(
    const float* __restrict__ a, const float* __restrict__ b,
    const float* __restrict__ c,
    float* __restrict__ da, float* __restrict__ db, float* __restrict__ dc)
{
    const float* s; float* d;
    if      (blockIdx.y == 0) { s = a; d = da; }
    else if (blockIdx.y == 1) { s = b; d = db; }
    else                      { s = c; d = dc; }
    int i = blockIdx.x * 256 + threadIdx.x;
    float4 v = ((const float4*)s)[i];
    uint4 o = make_uint4(f2tf(v.x), f2tf(v.y), f2tf(v.z), f2tf(v.w));
    ((uint4*)d)[i] = o;
}

__global__ __launch_bounds__(256) void round4(
    const float* __restrict__ a, const float* __restrict__ b,
    const float* __restrict__ c, const float* __restrict__ d,
    float* __restrict__ dst)
{
    const float* s;
    if      (blockIdx.y == 0) s = a;
    else if (blockIdx.y == 1) s = b;
    else if (blockIdx.y == 2) s = c;
    else                      s = d;
    int i = blockIdx.x * 256 + threadIdx.x;
    float4 v = ((const float4*)s)[i];
    uint4 o = make_uint4(f2tf(v.x), f2tf(v.y), f2tf(v.z), f2tf(v.w));
    ((uint4*)(dst + (size_t)blockIdx.y * DIM * DIM))[i] = o;
}

// ---------------------------------------------------------------------------
#define TPAD 20   // floats per padded row in GEMM tiles

__device__ __forceinline__ void cpa_tile(
    float (*dst)[TPAD], const float* __restrict__ src, int lda, int tid)
{
    #pragma unroll
    for (int i = 0; i < 2; i++) {
        int id = tid + i * 256;       // 0..511
        int r  = id >> 2;             // 0..127
        int c4 = (id & 3) << 2;       // 0,4,8,12
        cpa16(&dst[r][c4], src + (size_t)r * lda + c4);
    }
}

// One 16-K tile of MMAs; inputs are PRE-ROUNDED tf32 bits (no cvt).
__device__ __forceinline__ void tile_mma(
    const float (*As)[TPAD], const float (*Bs)[TPAD],
    float acc[4][4][4], int wm, int wn, int grp, int qd)
{
    #pragma unroll
    for (int kk = 0; kk < 16; kk += 8) {
        unsigned a[4][4], b[4][2];
        #pragma unroll
        for (int mi = 0; mi < 4; mi++) {
            int m = wm * 64 + mi * 16;
            a[mi][0] = __float_as_uint(As[m + grp    ][kk + qd    ]);
            a[mi][1] = __float_as_uint(As[m + grp + 8][kk + qd    ]);
            a[mi][2] = __float_as_uint(As[m + grp    ][kk + qd + 4]);
            a[mi][3] = __float_as_uint(As[m + grp + 8][kk + qd + 4]);
        }
        #pragma unroll
        for (int ni = 0; ni < 4; ni++) {
            int n = wn * 32 + ni * 8 + grp;
            b[ni][0] = __float_as_uint(Bs[n][kk + qd    ]);
            b[ni][1] = __float_as_uint(Bs[n][kk + qd + 4]);
        }
        #pragma unroll
        for (int mi = 0; mi < 4; mi++)
            #pragma unroll
            for (int ni = 0; ni < 4; ni++)
                mma_tf32(acc[mi][ni], a[mi][0], a[mi][1], a[mi][2], a[mi][3],
                         b[ni][0], b[ni][1]);
    }
}

// 3-stage cp.async mainloop over nk 16-K tiles (nk >= 3).
__device__ __forceinline__ void cpa_loop(
    const float* __restrict__ A, int lda,
    const float* __restrict__ B, int ldb, int nk,
    float (*As)[128][TPAD], float (*Bs)[128][TPAD],
    float acc[4][4][4], int tid, int wm, int wn, int grp, int qd)
{
    cpa_tile(As[0], A, lda, tid);
    cpa_tile(Bs[0], B, ldb, tid);
    CPA_COMMIT();
    cpa_tile(As[1], A + 16, lda, tid);
    cpa_tile(Bs[1], B + 16, ldb, tid);
    CPA_COMMIT();

    int cur = 0;
    for (int t = 0; t < nk; t++) {
        if (t < nk - 1) CPA_WAIT1(); else CPA_WAIT0();
        __syncthreads();
        tile_mma(As[cur], Bs[cur], acc, wm, wn, grp, qd);
        if (t + 2 < nk) {
            int nxt = cur + 2; if (nxt >= 3) nxt -= 3;
            cpa_tile(As[nxt], A + (t + 2) * 16, lda, tid);
            cpa_tile(Bs[nxt], B + (t + 2) * 16, ldb, tid);
            CPA_COMMIT();
        }
        if (++cur == 3) cur = 0;
    }
}

#define GEMM_SMEM (3 * 128 * TPAD * 4 * 2)          // 61440

// ---------------------------------------------------------------------------
// GEMM body: C[M,N] = A[M,K] @ W[N,K]^T + bias[N]; pre-rounded inputs.
// ---------------------------------------------------------------------------
__device__ __forceinline__ void gemm_body(
    const float* __restrict__ A, const float* __restrict__ W,
    const float* __restrict__ bias, float* __restrict__ C,
    int M, int N, int K, int round_out, float* sm)
{
    float (*As)[128][TPAD] = (float (*)[128][TPAD])sm;
    float (*Bs)[128][TPAD] = (float (*)[128][TPAD])(sm + 3 * 128 * TPAD);

    int tid = threadIdx.x;
    int warp = tid >> 5, lane = tid & 31;
    int wm = warp >> 2, wn = warp & 3;
    int grp = lane >> 2, qd = lane & 3;

    const float* Ab = A + (size_t)(blockIdx.y * 128) * K;
    const float* Wb = W + (size_t)(blockIdx.x * 128) * K;
    float acc[4][4][4] = {};
    cpa_loop(Ab, K, Wb, K, K / 16, As, Bs, acc, tid, wm, wn, grp, qd);

    int row0 = blockIdx.y * 128 + wm * 64;
    int col0 = blockIdx.x * 128 + wn * 32;
    #pragma unroll
    for (int mi = 0; mi < 4; mi++) {
        #pragma unroll
        for (int ni = 0; ni < 4; ni++) {
            int r  = row0 + mi * 16 + grp;
            int cc = col0 + ni * 8 + qd * 2;
            float b0 = bias[cc], b1 = bias[cc + 1];
            float v00 = acc[mi][ni][0] + b0, v01 = acc[mi][ni][1] + b1;
            float v10 = acc[mi][ni][2] + b0, v11 = acc[mi][ni][3] + b1;
            if (round_out) {
                v00 = __uint_as_float(f2tf(v00)); v01 = __uint_as_float(f2tf(v01));
                v10 = __uint_as_float(f2tf(v10)); v11 = __uint_as_float(f2tf(v11));
            }
            *(float2*)(C + (size_t)r * N + cc)       = make_float2(v00, v01);
            *(float2*)(C + (size_t)(r + 8) * N + cc) = make_float2(v10, v11);
        }
    }
}

// QKV fused: grid.z selects which projection this block computes.
__global__ __launch_bounds__(256, 2) void gemm_qkv(
    const float* __restrict__ rq, const float* __restrict__ rk,
    const float* __restrict__ rv, const float* __restrict__ w,
    const float* __restrict__ bq, const float* __restrict__ bk,
    const float* __restrict__ bv,
    float* __restrict__ oq, float* __restrict__ ok, float* __restrict__ ov)
{
    extern __shared__ float sm[];
    const float* A; const float* bias; float* C;
    int z = blockIdx.z;
    if      (z == 0) { A = rq; bias = bq; C = oq; }
    else if (z == 1) { A = rk; bias = bk; C = ok; }
    else             { A = rv; bias = bv; C = ov; }
    gemm_body(A, w + (size_t)z * DIM * DIM, bias, C, MTOT, DIM, DIM, 1, sm);
}

__global__ __launch_bounds__(256, 2) void gemm_cpa(
    const float* __restrict__ A, const float* __restrict__ W,
    const float* __restrict__ bias, float* __restrict__ C,
    int M, int N, int K, int round_out)
{
    extern __shared__ float sm[];
    gemm_body(A, W, bias, C, M, N, K, round_out, sm);
}

// ---------------------------------------------------------------------------
// scores: Q,K tiles fully resident (K=64), inputs pre-rounded (no cvt).
// Writes e = exp(x/8 - m_tile) + per-row-tile (max,sum) partials.
// ---------------------------------------------------------------------------
#define QPAD 68
#define SC_SMEM (2 * 128 * QPAD * 4)   // 69632

__global__ __launch_bounds__(256, 2) void attn_scores_v3(float* __restrict__ score)
{
    extern __shared__ float sm[];
    float (*Qs)[QPAD] = (float (*)[QPAD])sm;
    float (*Ks)[QPAD] = (float (*)[QPAD])(sm + 128 * QPAD);
    float (*rstat)[4] = (float (*)[4])sm;   // reuse after mainloop

    int tid = threadIdx.x;
    int warp = tid >> 5, lane = tid & 31;
    int wm = warp >> 2, wn = warp & 3;
    int grp = lane >> 2, qd = lane & 3;
    int bh = blockIdx.z, b = bh >> 4, h = bh & 15;

    const float* qb = g_q + (size_t)b * SEQ * DIM + (size_t)(blockIdx.y * 128) * DIM + h * DK;
    const float* kb = g_k + (size_t)b * SEQ * DIM + (size_t)(blockIdx.x * 128) * DIM + h * DK;

    #pragma unroll
    for (int i = 0; i < 8; i++) {
        int id = tid + i * 256;       // 0..2047
        int r  = id >> 4;             // 0..127
        int c4 = (id & 15) << 2;      // 0..60
        cpa16(&Qs[r][c4], qb + (size_t)r * DIM + c4);
    }
    #pragma unroll
    for (int i = 0; i < 8; i++) {
        int id = tid + i * 256;
        int r  = id >> 4;
        int c4 = (id & 15) << 2;
        cpa16(&Ks[r][c4], kb + (size_t)r * DIM + c4);
    }
    CPA_COMMIT();
    CPA_WAIT0();
    __syncthreads();

    float acc[4][4][4] = {};
    #pragma unroll
    for (int kk8 = 0; kk8 < 64; kk8 += 8) {
        unsigned a[4][4], bf[4][2];
        #pragma unroll
        for (int mi = 0; mi < 4; mi++) {
            int m = wm * 64 + mi * 16;
            a[mi][0] = __float_as_uint(Qs[m + grp    ][kk8 + qd    ]);
            a[mi][1] = __float_as_uint(Qs[m + grp + 8][kk8 + qd    ]);
            a[mi][2] = __float_as_uint(Qs[m + grp    ][kk8 + qd + 4]);
            a[mi][3] = __float_as_uint(Qs[m + grp + 8][kk8 + qd + 4]);
        }
        #pragma unroll
        for (int ni = 0; ni < 4; ni++) {
            int n = wn * 32 + ni * 8 + grp;
            bf[ni][0] = __float_as_uint(Ks[n][kk8 + qd    ]);
            bf[ni][1] = __float_as_uint(Ks[n][kk8 + qd + 4]);
        }
        #pragma unroll
        for (int mi = 0; mi < 4; mi++)
            #pragma unroll
            for (int ni = 0; ni < 4; ni++)
                mma_tf32(acc[mi][ni], a[mi][0], a[mi][1], a[mi][2], a[mi][3],
                         bf[ni][0], bf[ni][1]);
    }
    __syncthreads();   // tiles dead; rstat aliases smem

    const float alpha = 0.125f;
    #pragma unroll
    for (int mi = 0; mi < 4; mi++)
        #pragma unroll
        for (int ni = 0; ni < 4; ni++)
            #pragma unroll
            for (int j = 0; j < 4; j++)
                acc[mi][ni][j] *= alpha;

    float msel[4][2];
    #pragma unroll
    for (int mi = 0; mi < 4; mi++) {
        float mA = -1e30f, mB = -1e30f;
        #pragma unroll
        for (int ni = 0; ni < 4; ni++) {
            mA = fmaxf(mA, fmaxf(acc[mi][ni][0], acc[mi][ni][1]));
            mB = fmaxf(mB, fmaxf(acc[mi][ni][2], acc[mi][ni][3]));
        }
        mA = fmaxf(mA, __shfl_xor_sync(0xffffffffu, mA, 1));
        mA = fmaxf(mA, __shfl_xor_sync(0xffffffffu, mA, 2));
        mB = fmaxf(mB, __shfl_xor_sync(0xffffffffu, mB, 1));
        mB = fmaxf(mB, __shfl_xor_sync(0xffffffffu, mB, 2));
        int rA = wm * 64 + mi * 16 + grp;
        if (qd == 0) { rstat[rA][wn] = mA; rstat[rA + 8][wn] = mB; }
    }
    __syncthreads();
    #pragma unroll
    for (int mi = 0; mi < 4; mi++) {
        int rA = wm * 64 + mi * 16 + grp;
        msel[mi][0] = fmaxf(fmaxf(rstat[rA][0],     rstat[rA][1]),
                            fmaxf(rstat[rA][2],     rstat[rA][3]));
        msel[mi][1] = fmaxf(fmaxf(rstat[rA + 8][0], rstat[rA + 8][1]),
                            fmaxf(rstat[rA + 8][2], rstat[rA + 8][3]));
    }
    __syncthreads();

    float ssel[4][2];
    #pragma unroll
    for (int mi = 0; mi < 4; mi++) {
        float sA = 0.f, sB = 0.f;
        #pragma unroll
        for (int ni = 0; ni < 4; ni++) {
            acc[mi][ni][0] = __expf(acc[mi][ni][0] - msel[mi][0]);
            acc[mi][ni][1] = __expf(acc[mi][ni][1] - msel[mi][0]);
            acc[mi][ni][2] = __expf(acc[mi][ni][2] - msel[mi][1]);
            acc[mi][ni][3] = __expf(acc[mi][ni][3] - msel[mi][1]);
            sA += acc[mi][ni][0] + acc[mi][ni][1];
            sB += acc[mi][ni][2] + acc[mi][ni][3];
        }
        sA += __shfl_xor_sync(0xffffffffu, sA, 1);
        sA += __shfl_xor_sync(0xffffffffu, sA, 2);
        sB += __shfl_xor_sync(0xffffffffu, sB, 1);
        sB += __shfl_xor_sync(0xffffffffu, sB, 2);
        int rA = wm * 64 + mi * 16 + grp;
        if (qd == 0) { rstat[rA][wn] = sA; rstat[rA + 8][wn] = sB; }
    }
    __syncthreads();
    #pragma unroll
    for (int mi = 0; mi < 4; mi++) {
        int rA = wm * 64 + mi * 16 + grp;
        ssel[mi][0] = (rstat[rA][0]     + rstat[rA][1])
                    + (rstat[rA][2]     + rstat[rA][3]);
        ssel[mi][1] = (rstat[rA + 8][0] + rstat[rA + 8][1])
                    + (rstat[rA + 8][2] + rstat[rA + 8][3]);
    }

    float* ob = score + (size_t)bh * SEQ * SEQ;
    int row0 = blockIdx.y * 128 + wm * 64;
    int col0 = blockIdx.x * 128 + wn * 32;
    #pragma unroll
    for (int mi = 0; mi < 4; mi++) {
        #pragma unroll
        for (int ni = 0; ni < 4; ni++) {
            int r  = row0 + mi * 16 + grp;
            int cc = col0 + ni * 8 + qd * 2;
            *(float2*)(ob + (size_t)r * SEQ + cc) =
                make_float2(acc[mi][ni][0], acc[mi][ni][1]);
            *(float2*)(ob + (size_t)(r + 8) * SEQ + cc) =
                make_float2(acc[mi][ni][2], acc[mi][ni][3]);
        }
    }

    if (wn == 0 && qd == 0) {
        #pragma unroll
        for (int mi = 0; mi < 4; mi++) {
            #pragma unroll
            for (int half = 0; half < 2; half++) {
                int rowg = blockIdx.y * 128 + wm * 64 + mi * 16 + half * 8 + grp;
                size_t idx = ((size_t)(bh << 11) + rowg) * NCT + blockIdx.x;
                g_smax[idx] = msel[mi][half];
                g_ssum[idx] = ssel[mi][half];
            }
        }
    }
}

// ---------------------------------------------------------------------------
__global__ __launch_bounds__(256) void combine_stats()
{
    int gid = blockIdx.x * 256 + threadIdx.x;
    const float* mx = g_smax + (size_t)gid * NCT;
    const float* smv = g_ssum + (size_t)gid * NCT;
    float mv[NCT];
    float m = -1e30f;
    #pragma unroll
    for (int i = 0; i < NCT; i++) { mv[i] = mx[i]; m = fmaxf(m, mv[i]); }
    float s = 0.f;
    float ev[NCT];
    #pragma unroll
    for (int i = 0; i < NCT; i++) { ev[i] = __expf(mv[i] - m); s += smv[i] * ev[i]; }
    float inv = 1.0f / s;
    #pragma unroll
    for (int i = 0; i < NCT; i++) g_factor[(size_t)gid * NCT + i] = ev[i] * inv;
}

// ---------------------------------------------------------------------------
// PV v2: 256 threads, warps 2(M)x4(N) warp tile 64x16, CHK=32.
// Reads e, p = e*factor, writes final p in place, accumulates P@V.
// Ps row-major [128][36] (conflict-free float4 STS + fragment LDS).
// ---------------------------------------------------------------------------
#define CHK2 32
#define PVP 36
#define PV_SMEM ((128 * PVP + 2 * CHK2 * 72) * 4)   // 36864 bytes

__global__ __launch_bounds__(256, 2) void attn_pv2(float* __restrict__ score)
{
    extern __shared__ float smraw[];
    unsigned (*Ps)[PVP]       = (unsigned (*)[PVP])smraw;
    unsigned (*Vs)[CHK2][72]  = (unsigned (*)[CHK2][72])(smraw + 128 * PVP);

    int tid = threadIdx.x;
    int warp = tid >> 5, lane = tid & 31;
    int wm = warp >> 2, wn = warp & 3;     // 2 x 4
    int grp = lane >> 2, qd = lane & 3;
    int bh = blockIdx.y, b = bh >> 4, h = bh & 15;
    int row0 = blockIdx.x * 128;

    float* pb = score + (size_t)bh * SEQ * SEQ + (size_t)row0 * SEQ;
    const float* vb = g_v + (size_t)b * SEQ * DIM + h * DK;
    const float* fb = g_factor + ((size_t)(bh << 11) + row0) * NCT;

    float acc[4][2][4] = {};
    float4 pe[4]; float pf[4]; float4 pvv[2];

    // prologue: chunk 0
    #pragma unroll
    for (int i = 0; i < 4; i++) {
        int id = tid + i * 256;       // 0..1023
        int r  = id >> 3;             // 0..127
        int c4 = (id & 7) << 2;       // 0..28
        pe[i] = *(const float4*)(pb + (size_t)r * SEQ + c4);
        pf[i] = fb[r * NCT + 0];
    }
    #pragma unroll
    for (int i = 0; i < 2; i++) {
        int id = tid + i * 256;       // 0..511
        int r  = id >> 4;             // 0..31
        int c4 = (id & 15) << 2;
        pvv[i] = *(const float4*)(vb + (size_t)r * DIM + c4);
    }
    #pragma unroll
    for (int i = 0; i < 4; i++) {
        int id = tid + i * 256;
        int r  = id >> 3;
        int c4 = (id & 7) << 2;
        float4 p = make_float4(pe[i].x * pf[i], pe[i].y * pf[i],
                               pe[i].z * pf[i], pe[i].w * pf[i]);
        *(float4*)(pb + (size_t)r * SEQ + c4) = p;
        *(uint4*)&Ps[r][c4] = make_uint4(f2tf(p.x), f2tf(p.y), f2tf(p.z), f2tf(p.w));
    }
    #pragma unroll
    for (int i = 0; i < 2; i++) {
        int id = tid + i * 256;
        int r  = id >> 4;
        int c4 = (id & 15) << 2;
        *(uint4*)&Vs[0][r][c4] = make_uint4(
            __float_as_uint(pvv[i].x), __float_as_uint(pvv[i].y),
            __float_as_uint(pvv[i].z), __float_as_uint(pvv[i].w));
    }
    __syncthreads();

    const int NTCH = SEQ / CHK2;   // 64
    for (int t = 0; t < NTCH; t++) {
        int cur = t & 1;
        if (t + 1 < NTCH) {
            int ct = (t + 1) >> 2;
            #pragma unroll
            for (int i = 0; i < 4; i++) {
                int id = tid + i * 256;
                int r  = id >> 3;
                int c4 = (id & 7) << 2;
                pe[i] = *(const float4*)(pb + (size_t)r * SEQ + (t + 1) * CHK2 + c4);
                pf[i] = fb[r * NCT + ct];
            }
            #pragma unroll
            for (int i = 0; i < 2; i++) {
                int id = tid + i * 256;
                int r  = id >> 4;
                int c4 = (id & 15) << 2;
                pvv[i] = *(const float4*)(vb + (size_t)((t + 1) * CHK2 + r) * DIM + c4);
            }
        }

        // PV MMA: acc += P[128xCHK2] @ V[CHK2x64]; warp tile 64x16
        #pragma unroll
        for (int kk = 0; kk < CHK2; kk += 8) {
            unsigned a[4][4], bf[2][2];
            #pragma unroll
            for (int mi = 0; mi < 4; mi++) {
                int m = wm * 64 + mi * 16;
                a[mi][0] = Ps[m + grp    ][kk + qd    ];
                a[mi][1] = Ps[m + grp + 8][kk + qd    ];
                a[mi][2] = Ps[m + grp    ][kk + qd + 4];
                a[mi][3] = Ps[m + grp + 8][kk + qd + 4];
            }
            #pragma unroll
            for (int ni = 0; ni < 2; ni++) {
                int n = wn * 16 + ni * 8 + grp;
                bf[ni][0] = Vs[cur][kk + qd    ][n];
                bf[ni][1] = Vs[cur][kk + qd + 4][n];
            }
            #pragma unroll
            for (int mi = 0; mi < 4; mi++)
                #pragma unroll
                for (int ni = 0; ni < 2; ni++)
                    mma_tf32(acc[mi][ni], a[mi][0], a[mi][1], a[mi][2], a[mi][3],
                             bf[ni][0], bf[ni][1]);
        }
        __syncthreads();   // MMA reads of Ps/Vs[cur] done

        if (t + 1 < NTCH) {
            int nxt = cur ^ 1;
            #pragma unroll
            for (int i = 0; i < 4; i++) {
                int id = tid + i * 256;
                int r  = id >> 3;
                int c4 = (id & 7) << 2;
                float4 p = make_float4(pe[i].x * pf[i], pe[i].y * pf[i],
                                       pe[i].z * pf[i], pe[i].w * pf[i]);
                *(float4*)(pb + (size_t)r * SEQ + (t + 1) * CHK2 + c4) = p;
                *(uint4*)&Ps[r][c4] = make_uint4(f2tf(p.x), f2tf(p.y), f2tf(p.z), f2tf(p.w));
            }
            #pragma unroll
            for (int i = 0; i < 2; i++) {
                int id = tid + i * 256;
                int r  = id >> 4;
                int c4 = (id & 15) << 2;
                *(uint4*)&Vs[nxt][r][c4] = make_uint4(
                    __float_as_uint(pvv[i].x), __float_as_uint(pvv[i].y),
                    __float_as_uint(pvv[i].z), __float_as_uint(pvv[i].w));
            }
            __syncthreads();   // new Ps/Vs visible
        }
    }

    // store blended pre-rounded to tf32 bits for the cvt-free out-proj GEMM
    float* ob = g_bl + (size_t)b * SEQ * DIM;
    int r0 = row0 + wm * 64;
    int c0 = h * DK + wn * 16;
    #pragma unroll
    for (int mi = 0; mi < 4; mi++) {
        #pragma unroll
        for (int ni = 0; ni < 2; ni++) {
            int r  = r0 + mi * 16 + grp;
            int cc = c0 + ni * 8 + qd * 2;
            float2 o0 = make_float2(__uint_as_float(f2tf(acc[mi][ni][0])),
                                    __uint_as_float(f2tf(acc[mi][ni][1])));
            float2 o1 = make_float2(__uint_as_float(f2tf(acc[mi][ni][2])),
                                    __uint_as_float(f2tf(acc[mi][ni][3])));
            *(float2*)(ob + (size_t)r * DIM + cc)       = o0;
            *(float2*)(ob + (size_t)(r + 8) * DIM + cc) = o1;
        }
    }
}

// ---------------------------------------------------------------------------
extern "C" void kernel_launch(void* const* d_in, const int* in_sizes, int n_in,
                              void* d_out, int out_size)
{
    const float* query = (const float*)d_in[0];
    const float* key   = (const float*)d_in[1];
    const float* value = (const float*)d_in[2];
    const float* Wq    = (const float*)d_in[3];
    const float* bq    = (const float*)d_in[4];
    const float* Wk    = (const float*)d_in[5];
    const float* bk    = (const float*)d_in[6];
    const float* Wv    = (const float*)d_in[7];
    const float* bv    = (const float*)d_in[8];
    const float* Wo    = (const float*)d_in[9];
    const float* bo    = (const float*)d_in[10];

    float* out   = (float*)d_out;                          // [B,S,D]
    float* score = out + (size_t)BSZ * SEQ * DIM;          // [B,H,S,S]

    float *pq, *pk, *pv, *pbl, *prq, *prk, *prv, *pw;
    cudaGetSymbolAddress((void**)&pq,  g_q);
    cudaGetSymbolAddress((void**)&pk,  g_k);
    cudaGetSymbolAddress((void**)&pv,  g_v);
    cudaGetSymbolAddress((void**)&pbl, g_bl);
    cudaGetSymbolAddress((void**)&prq, g_rq);
    cudaGetSymbolAddress((void**)&prk, g_rk);
    cudaGetSymbolAddress((void**)&prv, g_rv);
    cudaGetSymbolAddress((void**)&pw,  g_w);

    cudaFuncSetAttribute(gemm_cpa,
        cudaFuncAttributeMaxDynamicSharedMemorySize, GEMM_SMEM);
    cudaFuncSetAttribute(gemm_qkv,
        cudaFuncAttributeMaxDynamicSharedMemorySize, GEMM_SMEM);
    cudaFuncSetAttribute(attn_scores_v3,
        cudaFuncAttributeMaxDynamicSharedMemorySize, SC_SMEM);
    cudaFuncSetAttribute(attn_pv2,
        cudaFuncAttributeMaxDynamicSharedMemorySize, PV_SMEM);

    // pre-round inputs + weights to tf32 bits
    round3<<<dim3(MTOT * DIM / 4 / 256, 3), 256>>>(query, key, value, prq, prk, prv);
    round4<<<dim3(DIM * DIM / 4 / 256, 4), 256>>>(Wq, Wk, Wv, Wo, pw);

    dim3 gqkv(DIM / 128, MTOT / 128, 3);   // (8, 32, 3)
    gemm_qkv<<<gqkv, 256, GEMM_SMEM>>>(prq, prk, prv, pw, bq, bk, bv, pq, pk, pv);

    attn_scores_v3<<<dim3(SEQ / 128, SEQ / 128, BH), 256, SC_SMEM>>>(score);
    combine_stats<<<NROWS / 256, 256>>>();
    attn_pv2<<<dim3(SEQ / 128, BH), 256, PV_SMEM>>>(score);

    dim3 gp(DIM / 128, MTOT / 128);   // (8, 32)
    gemm_cpa<<<gp, 256, GEMM_SMEM>>>(pbl, pw + 3 * DIM * DIM, bo, out, MTOT, DIM, DIM, 0);
}

// round 14
// speedup vs baseline: 1.1555x; 1.0059x over previous
#include <cuda_runtime.h>
#include <math.h>
#include <stdint.h>

#define BSZ 2
#define SEQ 2048
#define DIM 1024
#define NH  16
#define DK  64
#define BH  (BSZ*NH)   // 32
#define MTOT (BSZ*SEQ) // 4096
#define NROWS (BH*SEQ) // 65536
#define NCT  16        // col tiles of 128 per row

// Scratch (allocation-free rule: __device__ globals)
__device__ float g_q [BSZ*SEQ*DIM];
__device__ float g_k [BSZ*SEQ*DIM];
__device__ float g_v [BSZ*SEQ*DIM];
__device__ float g_bl[BSZ*SEQ*DIM];
__device__ float g_rq[BSZ*SEQ*DIM];     // tf32-rounded inputs
__device__ float g_rk[BSZ*SEQ*DIM];
__device__ float g_rv[BSZ*SEQ*DIM];
__device__ float g_w [4*DIM*DIM];       // tf32-rounded weights
__device__ float g_smax  [NROWS*NCT];
__device__ float g_ssum  [NROWS*NCT];
__device__ float g_factor[NROWS*NCT];

// ---------------------------------------------------------------------------
// helpers
// ---------------------------------------------------------------------------
__device__ __forceinline__ unsigned f2tf(float x) {
    unsigned r;
    asm("cvt.rna.tf32.f32 %0, %1;" : "=r"(r) : "f"(x));
    return r;
}

__device__ __forceinline__ void mma_tf32(float c[4],
    unsigned a0, unsigned a1, unsigned a2, unsigned a3,
    unsigned b0, unsigned b1)
{
    asm volatile(
        "mma.sync.aligned.m16n8k8.row.col.f32.tf32.tf32.f32 "
        "{%0,%1,%2,%3}, {%4,%5,%6,%7}, {%8,%9}, {%0,%1,%2,%3};\n"
        : "+f"(c[0]), "+f"(c[1]), "+f"(c[2]), "+f"(c[3])
        : "r"(a0), "r"(a1), "r"(a2), "r"(a3), "r"(b0), "r"(b1));
}

__device__ __forceinline__ unsigned smem_u32(const void* p) {
    unsigned a;
    asm("{ .reg .u64 t; cvta.to.shared.u64 t, %1; cvt.u32.u64 %0, t; }"
        : "=r"(a) : "l"(p));
    return a;
}

#define CPA_COMMIT() asm volatile("cp.async.commit_group;" ::: "memory")
#define CPA_WAIT1()  asm volatile("cp.async.wait_group 1;" ::: "memory")
#define CPA_WAIT0()  asm volatile("cp.async.wait_group 0;" ::: "memory")

__device__ __forceinline__ void cpa16(const void* smem_dst, const float* gsrc) {
    unsigned sa = smem_u32(smem_dst);
    asm volatile("cp.async.cg.shared.global [%0], [%1], 16;"
                 :: "r"(sa), "l"(gsrc) : "memory");
}

// ---------------------------------------------------------------------------
// pre-round kernels (tf32 bits, idempotent w.r.t. later MMA use)
// ---------------------------------------------------------------------------
__global__ __launch_bounds__(256) void round3(
    const float* __restrict__ a, const float* __restrict__ b,
    const float* __restrict__ c,
    float* __restrict__ da, float* __restrict__ db, float* __restrict__ dc)
{
    const float* s; float* d;
    if      (blockIdx.y == 0) { s = a; d = da; }
    else if (blockIdx.y == 1) { s = b; d = db; }
    else                      { s = c; d = dc; }
    int i = blockIdx.x * 256 + threadIdx.x;
    float4 v = ((const float4*)s)[i];
    uint4 o = make_uint4(f2tf(v.x), f2tf(v.y), f2tf(v.z), f2tf(v.w));
    ((uint4*)d)[i] = o;
}

__global__ __launch_bounds__(256) void round4(
    const float* __restrict__ a, const float* __restrict__ b,
    const float* __restrict__ c, const float* __restrict__ d,
    float* __restrict__ dst)
{
    const float* s;
    if      (blockIdx.y == 0) s = a;
    else if (blockIdx.y == 1) s = b;
    else if (blockIdx.y == 2) s = c;
    else                      s = d;
    int i = blockIdx.x * 256 + threadIdx.x;
    float4 v = ((const float4*)s)[i];
    uint4 o = make_uint4(f2tf(v.x), f2tf(v.y), f2tf(v.z), f2tf(v.w));
    ((uint4*)(dst + (size_t)blockIdx.y * DIM * DIM))[i] = o;
}

// ---------------------------------------------------------------------------
#define TPAD 20   // floats per padded row in GEMM tiles

__device__ __forceinline__ void cpa_tile(
    float (*dst)[TPAD], const float* __restrict__ src, int lda, int tid)
{
    #pragma unroll
    for (int i = 0; i < 2; i++) {
        int id = tid + i * 256;       // 0..511
        int r  = id >> 2;             // 0..127
        int c4 = (id & 3) << 2;       // 0,4,8,12
        cpa16(&dst[r][c4], src + (size_t)r * lda + c4);
    }
}

// One 16-K tile of MMAs; inputs are PRE-ROUNDED tf32 bits (no cvt).
__device__ __forceinline__ void tile_mma(
    const float (*As)[TPAD], const float (*Bs)[TPAD],
    float acc[4][4][4], int wm, int wn, int grp, int qd)
{
    #pragma unroll
    for (int kk = 0; kk < 16; kk += 8) {
        unsigned a[4][4], b[4][2];
        #pragma unroll
        for (int mi = 0; mi < 4; mi++) {
            int m = wm * 64 + mi * 16;
            a[mi][0] = __float_as_uint(As[m + grp    ][kk + qd    ]);
            a[mi][1] = __float_as_uint(As[m + grp + 8][kk + qd    ]);
            a[mi][2] = __float_as_uint(As[m + grp    ][kk + qd + 4]);
            a[mi][3] = __float_as_uint(As[m + grp + 8][kk + qd + 4]);
        }
        #pragma unroll
        for (int ni = 0; ni < 4; ni++) {
            int n = wn * 32 + ni * 8 + grp;
            b[ni][0] = __float_as_uint(Bs[n][kk + qd    ]);
            b[ni][1] = __float_as_uint(Bs[n][kk + qd + 4]);
        }
        #pragma unroll
        for (int mi = 0; mi < 4; mi++)
            #pragma unroll
            for (int ni = 0; ni < 4; ni++)
                mma_tf32(acc[mi][ni], a[mi][0], a[mi][1], a[mi][2], a[mi][3],
                         b[ni][0], b[ni][1]);
    }
}

// 3-stage cp.async mainloop over nk 16-K tiles (nk >= 3).
__device__ __forceinline__ void cpa_loop(
    const float* __restrict__ A, int lda,
    const float* __restrict__ B, int ldb, int nk,
    float (*As)[128][TPAD], float (*Bs)[128][TPAD],
    float acc[4][4][4], int tid, int wm, int wn, int grp, int qd)
{
    cpa_tile(As[0], A, lda, tid);
    cpa_tile(Bs[0], B, ldb, tid);
    CPA_COMMIT();
    cpa_tile(As[1], A + 16, lda, tid);
    cpa_tile(Bs[1], B + 16, ldb, tid);
    CPA_COMMIT();

    int cur = 0;
    for (int t = 0; t < nk; t++) {
        if (t < nk - 1) CPA_WAIT1(); else CPA_WAIT0();
        __syncthreads();
        tile_mma(As[cur], Bs[cur], acc, wm, wn, grp, qd);
        if (t + 2 < nk) {
            int nxt = cur + 2; if (nxt >= 3) nxt -= 3;
            cpa_tile(As[nxt], A + (t + 2) * 16, lda, tid);
            cpa_tile(Bs[nxt], B + (t + 2) * 16, ldb, tid);
            CPA_COMMIT();
        }
        if (++cur == 3) cur = 0;
    }
}

#define GEMM_SMEM (3 * 128 * TPAD * 4 * 2)          // 61440

// ---------------------------------------------------------------------------
// GEMM body: C[M,N] = A[M,K] @ W[N,K]^T + bias[N]; pre-rounded inputs.
// ---------------------------------------------------------------------------
__device__ __forceinline__ void gemm_body(
    const float* __restrict__ A, const float* __restrict__ W,
    const float* __restrict__ bias, float* __restrict__ C,
    int M, int N, int K, int round_out, float* sm)
{
    float (*As)[128][TPAD] = (float (*)[128][TPAD])sm;
    float (*Bs)[128][TPAD] = (float (*)[128][TPAD])(sm + 3 * 128 * TPAD);

    int tid = threadIdx.x;
    int warp = tid >> 5, lane = tid & 31;
    int wm = warp >> 2, wn = warp & 3;
    int grp = lane >> 2, qd = lane & 3;

    const float* Ab = A + (size_t)(blockIdx.y * 128) * K;
    const float* Wb = W + (size_t)(blockIdx.x * 128) * K;
    float acc[4][4][4] = {};
    cpa_loop(Ab, K, Wb, K, K / 16, As, Bs, acc, tid, wm, wn, grp, qd);

    int row0 = blockIdx.y * 128 + wm * 64;
    int col0 = blockIdx.x * 128 + wn * 32;
    #pragma unroll
    for (int mi = 0; mi < 4; mi++) {
        #pragma unroll
        for (int ni = 0; ni < 4; ni++) {
            int r  = row0 + mi * 16 + grp;
            int cc = col0 + ni * 8 + qd * 2;
            float b0 = bias[cc], b1 = bias[cc + 1];
            float v00 = acc[mi][ni][0] + b0, v01 = acc[mi][ni][1] + b1;
            float v10 = acc[mi][ni][2] + b0, v11 = acc[mi][ni][3] + b1;
            if (round_out) {
                v00 = __uint_as_float(f2tf(v00)); v01 = __uint_as_float(f2tf(v01));
                v10 = __uint_as_float(f2tf(v10)); v11 = __uint_as_float(f2tf(v11));
            }
            *(float2*)(C + (size_t)r * N + cc)       = make_float2(v00, v01);
            *(float2*)(C + (size_t)(r + 8) * N + cc) = make_float2(v10, v11);
        }
    }
}

// QKV fused: grid.z selects which projection this block computes.
__global__ __launch_bounds__(256, 2) void gemm_qkv(
    const float* __restrict__ rq, const float* __restrict__ rk,
    const float* __restrict__ rv, const float* __restrict__ w,
    const float* __restrict__ bq, const float* __restrict__ bk,
    const float* __restrict__ bv,
    float* __restrict__ oq, float* __restrict__ ok, float* __restrict__ ov)
{
    extern __shared__ float sm[];
    const float* A; const float* bias; float* C;
    int z = blockIdx.z;
    if      (z == 0) { A = rq; bias = bq; C = oq; }
    else if (z == 1) { A = rk; bias = bk; C = ok; }
    else             { A = rv; bias = bv; C = ov; }
    gemm_body(A, w + (size_t)z * DIM * DIM, bias, C, MTOT, DIM, DIM, 1, sm);
}

__global__ __launch_bounds__(256, 2) void gemm_cpa(
    const float* __restrict__ A, const float* __restrict__ W,
    const float* __restrict__ bias, float* __restrict__ C,
    int M, int N, int K, int round_out)
{
    extern __shared__ float sm[];
    gemm_body(A, W, bias, C, M, N, K, round_out, sm);
}

// ---------------------------------------------------------------------------
// scores: Q,K tiles fully resident (K=64), inputs pre-rounded (no cvt).
// Writes e = exp(x/8 - m_tile) + per-row-tile (max,sum) partials.
// ---------------------------------------------------------------------------
#define QPAD 68
#define SC_SMEM (2 * 128 * QPAD * 4)   // 69632

__global__ __launch_bounds__(256, 2) void attn_scores_v3(float* __restrict__ score)
{
    extern __shared__ float sm[];
    float (*Qs)[QPAD] = (float (*)[QPAD])sm;
    float (*Ks)[QPAD] = (float (*)[QPAD])(sm + 128 * QPAD);
    float (*rstat)[4] = (float (*)[4])sm;   // reuse after mainloop

    int tid = threadIdx.x;
    int warp = tid >> 5, lane = tid & 31;
    int wm = warp >> 2, wn = warp & 3;
    int grp = lane >> 2, qd = lane & 3;
    int bh = blockIdx.z, b = bh >> 4, h = bh & 15;

    const float* qb = g_q + (size_t)b * SEQ * DIM + (size_t)(blockIdx.y * 128) * DIM + h * DK;
    const float* kb = g_k + (size_t)b * SEQ * DIM + (size_t)(blockIdx.x * 128) * DIM + h * DK;

    #pragma unroll
    for (int i = 0; i < 8; i++) {
        int id = tid + i * 256;       // 0..2047
        int r  = id >> 4;             // 0..127
        int c4 = (id & 15) << 2;      // 0..60
        cpa16(&Qs[r][c4], qb + (size_t)r * DIM + c4);
    }
    #pragma unroll
    for (int i = 0; i < 8; i++) {
        int id = tid + i * 256;
        int r  = id >> 4;
        int c4 = (id & 15) << 2;
        cpa16(&Ks[r][c4], kb + (size_t)r * DIM + c4);
    }
    CPA_COMMIT();
    CPA_WAIT0();
    __syncthreads();

    float acc[4][4][4] = {};
    #pragma unroll
    for (int kk8 = 0; kk8 < 64; kk8 += 8) {
        unsigned a[4][4], bf[4][2];
        #pragma unroll
        for (int mi = 0; mi < 4; mi++) {
            int m = wm * 64 + mi * 16;
            a[mi][0] = __float_as_uint(Qs[m + grp    ][kk8 + qd    ]);
            a[mi][1] = __float_as_uint(Qs[m + grp + 8][kk8 + qd    ]);
            a[mi][2] = __float_as_uint(Qs[m + grp    ][kk8 + qd + 4]);
            a[mi][3] = __float_as_uint(Qs[m + grp + 8][kk8 + qd + 4]);
        }
        #pragma unroll
        for (int ni = 0; ni < 4; ni++) {
            int n = wn * 32 + ni * 8 + grp;
            bf[ni][0] = __float_as_uint(Ks[n][kk8 + qd    ]);
            bf[ni][1] = __float_as_uint(Ks[n][kk8 + qd + 4]);
        }
        #pragma unroll
        for (int mi = 0; mi < 4; mi++)
            #pragma unroll
            for (int ni = 0; ni < 4; ni++)
                mma_tf32(acc[mi][ni], a[mi][0], a[mi][1], a[mi][2], a[mi][3],
                         bf[ni][0], bf[ni][1]);
    }
    __syncthreads();   // tiles dead; rstat aliases smem

    const float alpha = 0.125f;
    #pragma unroll
    for (int mi = 0; mi < 4; mi++)
        #pragma unroll
        for (int ni = 0; ni < 4; ni++)
            #pragma unroll
            for (int j = 0; j < 4; j++)
                acc[mi][ni][j] *= alpha;

    float msel[4][2];
    #pragma unroll
    for (int mi = 0; mi < 4; mi++) {
        float mA = -1e30f, mB = -1e30f;
        #pragma unroll
        for (int ni = 0; ni < 4; ni++) {
            mA = fmaxf(mA, fmaxf(acc[mi][ni][0], acc[mi][ni][1]));
            mB = fmaxf(mB, fmaxf(acc[mi][ni][2], acc[mi][ni][3]));
        }
        mA = fmaxf(mA, __shfl_xor_sync(0xffffffffu, mA, 1));
        mA = fmaxf(mA, __shfl_xor_sync(0xffffffffu, mA, 2));
        mB = fmaxf(mB, __shfl_xor_sync(0xffffffffu, mB, 1));
        mB = fmaxf(mB, __shfl_xor_sync(0xffffffffu, mB, 2));
        int rA = wm * 64 + mi * 16 + grp;
        if (qd == 0) { rstat[rA][wn] = mA; rstat[rA + 8][wn] = mB; }
    }
    __syncthreads();
    #pragma unroll
    for (int mi = 0; mi < 4; mi++) {
        int rA = wm * 64 + mi * 16 + grp;
        msel[mi][0] = fmaxf(fmaxf(rstat[rA][0],     rstat[rA][1]),
                            fmaxf(rstat[rA][2],     rstat[rA][3]));
        msel[mi][1] = fmaxf(fmaxf(rstat[rA + 8][0], rstat[rA + 8][1]),
                            fmaxf(rstat[rA + 8][2], rstat[rA + 8][3]));
    }
    __syncthreads();

    float ssel[4][2];
    #pragma unroll
    for (int mi = 0; mi < 4; mi++) {
        float sA = 0.f, sB = 0.f;
        #pragma unroll
        for (int ni = 0; ni < 4; ni++) {
            acc[mi][ni][0] = __expf(acc[mi][ni][0] - msel[mi][0]);
            acc[mi][ni][1] = __expf(acc[mi][ni][1] - msel[mi][0]);
            acc[mi][ni][2] = __expf(acc[mi][ni][2] - msel[mi][1]);
            acc[mi][ni][3] = __expf(acc[mi][ni][3] - msel[mi][1]);
            sA += acc[mi][ni][0] + acc[mi][ni][1];
            sB += acc[mi][ni][2] + acc[mi][ni][3];
        }
        sA += __shfl_xor_sync(0xffffffffu, sA, 1);
        sA += __shfl_xor_sync(0xffffffffu, sA, 2);
        sB += __shfl_xor_sync(0xffffffffu, sB, 1);
        sB += __shfl_xor_sync(0xffffffffu, sB, 2);
        int rA = wm * 64 + mi * 16 + grp;
        if (qd == 0) { rstat[rA][wn] = sA; rstat[rA + 8][wn] = sB; }
    }
    __syncthreads();
    #pragma unroll
    for (int mi = 0; mi < 4; mi++) {
        int rA = wm * 64 + mi * 16 + grp;
        ssel[mi][0] = (rstat[rA][0]     + rstat[rA][1])
                    + (rstat[rA][2]     + rstat[rA][3]);
        ssel[mi][1] = (rstat[rA + 8][0] + rstat[rA + 8][1])
                    + (rstat[rA + 8][2] + rstat[rA + 8][3]);
    }

    float* ob = score + (size_t)bh * SEQ * SEQ;
    int row0 = blockIdx.y * 128 + wm * 64;
    int col0 = blockIdx.x * 128 + wn * 32;
    #pragma unroll
    for (int mi = 0; mi < 4; mi++) {
        #pragma unroll
        for (int ni = 0; ni < 4; ni++) {
            int r  = row0 + mi * 16 + grp;
            int cc = col0 + ni * 8 + qd * 2;
            *(float2*)(ob + (size_t)r * SEQ + cc) =
                make_float2(acc[mi][ni][0], acc[mi][ni][1]);
            *(float2*)(ob + (size_t)(r + 8) * SEQ + cc) =
                make_float2(acc[mi][ni][2], acc[mi][ni][3]);
        }
    }

    if (wn == 0 && qd == 0) {
        #pragma unroll
        for (int mi = 0; mi < 4; mi++) {
            #pragma unroll
            for (int half = 0; half < 2; half++) {
                int rowg = blockIdx.y * 128 + wm * 64 + mi * 16 + half * 8 + grp;
                size_t idx = ((size_t)(bh << 11) + rowg) * NCT + blockIdx.x;
                g_smax[idx] = msel[mi][half];
                g_ssum[idx] = ssel[mi][half];
            }
        }
    }
}

// ---------------------------------------------------------------------------
__global__ __launch_bounds__(256) void combine_stats()
{
    int gid = blockIdx.x * 256 + threadIdx.x;
    const float* mx = g_smax + (size_t)gid * NCT;
    const float* smv = g_ssum + (size_t)gid * NCT;
    float mv[NCT];
    float m = -1e30f;
    #pragma unroll
    for (int i = 0; i < NCT; i++) { mv[i] = mx[i]; m = fmaxf(m, mv[i]); }
    float s = 0.f;
    float ev[NCT];
    #pragma unroll
    for (int i = 0; i < NCT; i++) { ev[i] = __expf(mv[i] - m); s += smv[i] * ev[i]; }
    float inv = 1.0f / s;
    #pragma unroll
    for (int i = 0; i < NCT; i++) g_factor[(size_t)gid * NCT + i] = ev[i] * inv;
}

// ---------------------------------------------------------------------------
// PV v2: 256 threads, warps 2(M)x4(N) warp tile 64x16, CHK=32.
// Reads e, p = e*factor, writes final p in place, accumulates P@V.
// Ps row-major [128][36] (conflict-free float4 STS + fragment LDS).
// ---------------------------------------------------------------------------
#define CHK2 32
#define PVP 36
#define PV_SMEM ((128 * PVP + 2 * CHK2 * 72) * 4)   // 36864 bytes

__global__ __launch_bounds__(256, 2) void attn_pv2(float* __restrict__ score)
{
    extern __shared__ float smraw[];
    unsigned (*Ps)[PVP]       = (unsigned (*)[PVP])smraw;
    unsigned (*Vs)[CHK2][72]  = (unsigned (*)[CHK2][72])(smraw + 128 * PVP);

    int tid = threadIdx.x;
    int warp = tid >> 5, lane = tid & 31;
    int wm = warp >> 2, wn = warp & 3;     // 2 x 4
    int grp = lane >> 2, qd = lane & 3;
    int bh = blockIdx.y, b = bh >> 4, h = bh & 15;
    int row0 = blockIdx.x * 128;

    float* pb = score + (size_t)bh * SEQ * SEQ + (size_t)row0 * SEQ;
    const float* vb = g_v + (size_t)b * SEQ * DIM + h * DK;
    const float* fb = g_factor + ((size_t)(bh << 11) + row0) * NCT;

    float acc[4][2][4] = {};
    float4 pe[4]; float pf[4]; float4 pvv[2];

    // prologue: chunk 0
    #pragma unroll
    for (int i = 0; i < 4; i++) {
        int id = tid + i * 256;       // 0..1023
        int r  = id >> 3;             // 0..127
        int c4 = (id & 7) << 2;       // 0..28
        pe[i] = *(const float4*)(pb + (size_t)r * SEQ + c4);
        pf[i] = fb[r * NCT + 0];
    }
    #pragma unroll
    for (int i = 0; i < 2; i++) {
        int id = tid + i * 256;       // 0..511
        int r  = id >> 4;             // 0..31
        int c4 = (id & 15) << 2;
        pvv[i] = *(const float4*)(vb + (size_t)r * DIM + c4);
    }
    #pragma unroll
    for (int i = 0; i < 4; i++) {
        int id = tid + i * 256;
        int r  = id >> 3;
        int c4 = (id & 7) << 2;
        float4 p = make_float4(pe[i].x * pf[i], pe[i].y * pf[i],
                               pe[i].z * pf[i], pe[i].w * pf[i]);
        *(float4*)(pb + (size_t)r * SEQ + c4) = p;
        *(uint4*)&Ps[r][c4] = make_uint4(f2tf(p.x), f2tf(p.y), f2tf(p.z), f2tf(p.w));
    }
    #pragma unroll
    for (int i = 0; i < 2; i++) {
        int id = tid + i * 256;
        int r  = id >> 4;
        int c4 = (id & 15) << 2;
        *(uint4*)&Vs[0][r][c4] = make_uint4(
            __float_as_uint(pvv[i].x), __float_as_uint(pvv[i].y),
            __float_as_uint(pvv[i].z), __float_as_uint(pvv[i].w));
    }
    __syncthreads();

    const int NTCH = SEQ / CHK2;   // 64
    for (int t = 0; t < NTCH; t++) {
        int cur = t & 1;
        if (t + 1 < NTCH) {
            int ct = (t + 1) >> 2;
            #pragma unroll
            for (int i = 0; i < 4; i++) {
                int id = tid + i * 256;
                int r  = id >> 3;
                int c4 = (id & 7) << 2;
                pe[i] = *(const float4*)(pb + (size_t)r * SEQ + (t + 1) * CHK2 + c4);
                pf[i] = fb[r * NCT + ct];
            }
            #pragma unroll
            for (int i = 0; i < 2; i++) {
                int id = tid + i * 256;
                int r  = id >> 4;
                int c4 = (id & 15) << 2;
                pvv[i] = *(const float4*)(vb + (size_t)((t + 1) * CHK2 + r) * DIM + c4);
            }
        }

        // PV MMA: acc += P[128xCHK2] @ V[CHK2x64]; warp tile 64x16
        #pragma unroll
        for (int kk = 0; kk < CHK2; kk += 8) {
            unsigned a[4][4], bf[2][2];
            #pragma unroll
            for (int mi = 0; mi < 4; mi++) {
                int m = wm * 64 + mi * 16;
                a[mi][0] = Ps[m + grp    ][kk + qd    ];
                a[mi][1] = Ps[m + grp + 8][kk + qd    ];
                a[mi][2] = Ps[m + grp    ][kk + qd + 4];
                a[mi][3] = Ps[m + grp + 8][kk + qd + 4];
            }
            #pragma unroll
            for (int ni = 0; ni < 2; ni++) {
                int n = wn * 16 + ni * 8 + grp;
                bf[ni][0] = Vs[cur][kk + qd    ][n];
                bf[ni][1] = Vs[cur][kk + qd + 4][n];
            }
            #pragma unroll
            for (int mi = 0; mi < 4; mi++)
                #pragma unroll
                for (int ni = 0; ni < 2; ni++)
                    mma_tf32(acc[mi][ni], a[mi][0], a[mi][1], a[mi][2], a[mi][3],
                             bf[ni][0], bf[ni][1]);
        }
        __syncthreads();   // MMA reads of Ps/Vs[cur] done

        if (t + 1 < NTCH) {
            int nxt = cur ^ 1;
            #pragma unroll
            for (int i = 0; i < 4; i++) {
                int id = tid + i * 256;
                int r  = id >> 3;
                int c4 = (id & 7) << 2;
                float4 p = make_float4(pe[i].x * pf[i], pe[i].y * pf[i],
                                       pe[i].z * pf[i], pe[i].w * pf[i]);
                *(float4*)(pb + (size_t)r * SEQ + (t + 1) * CHK2 + c4) = p;
                *(uint4*)&Ps[r][c4] = make_uint4(f2tf(p.x), f2tf(p.y), f2tf(p.z), f2tf(p.w));
            }
            #pragma unroll
            for (int i = 0; i < 2; i++) {
                int id = tid + i * 256;
                int r  = id >> 4;
                int c4 = (id & 15) << 2;
                *(uint4*)&Vs[nxt][r][c4] = make_uint4(
                    __float_as_uint(pvv[i].x), __float_as_uint(pvv[i].y),
                    __float_as_uint(pvv[i].z), __float_as_uint(pvv[i].w));
            }
            __syncthreads();   // new Ps/Vs visible
        }
    }

    // store blended pre-rounded to tf32 bits for the cvt-free out-proj GEMM
    float* ob = g_bl + (size_t)b * SEQ * DIM;
    int r0 = row0 + wm * 64;
    int c0 = h * DK + wn * 16;
    #pragma unroll
    for (int mi = 0; mi < 4; mi++) {
        #pragma unroll
        for (int ni = 0; ni < 2; ni++) {
            int r  = r0 + mi * 16 + grp;
            int cc = c0 + ni * 8 + qd * 2;
            float2 o0 = make_float2(__uint_as_float(f2tf(acc[mi][ni][0])),
                                    __uint_as_float(f2tf(acc[mi][ni][1])));
            float2 o1 = make_float2(__uint_as_float(f2tf(acc[mi][ni][2])),
                                    __uint_as_float(f2tf(acc[mi][ni][3])));
            *(float2*)(ob + (size_t)r * DIM + cc)       = o0;
            *(float2*)(ob + (size_t)(r + 8) * DIM + cc) = o1;
        }
    }
}

// ---------------------------------------------------------------------------
extern "C" void kernel_launch(void* const* d_in, const int* in_sizes, int n_in,
                              void* d_out, int out_size)
{
    const float* query = (const float*)d_in[0];
    const float* key   = (const float*)d_in[1];
    const float* value = (const float*)d_in[2];
    const float* Wq    = (const float*)d_in[3];
    const float* bq    = (const float*)d_in[4];
    const float* Wk    = (const float*)d_in[5];
    const float* bk    = (const float*)d_in[6];
    const float* Wv    = (const float*)d_in[7];
    const float* bv    = (const float*)d_in[8];
    const float* Wo    = (const float*)d_in[9];
    const float* bo    = (const float*)d_in[10];

    float* out   = (float*)d_out;                          // [B,S,D]
    float* score = out + (size_t)BSZ * SEQ * DIM;          // [B,H,S,S]

    float *pq, *pk, *pv, *pbl, *prq, *prk, *prv, *pw;
    cudaGetSymbolAddress((void**)&pq,  g_q);
    cudaGetSymbolAddress((void**)&pk,  g_k);
    cudaGetSymbolAddress((void**)&pv,  g_v);
    cudaGetSymbolAddress((void**)&pbl, g_bl);
    cudaGetSymbolAddress((void**)&prq, g_rq);
    cudaGetSymbolAddress((void**)&prk, g_rk);
    cudaGetSymbolAddress((void**)&prv, g_rv);
    cudaGetSymbolAddress((void**)&pw,  g_w);

    cudaFuncSetAttribute(gemm_cpa,
        cudaFuncAttributeMaxDynamicSharedMemorySize, GEMM_SMEM);
    cudaFuncSetAttribute(gemm_qkv,
        cudaFuncAttributeMaxDynamicSharedMemorySize, GEMM_SMEM);
    cudaFuncSetAttribute(attn_scores_v3,
        cudaFuncAttributeMaxDynamicSharedMemorySize, SC_SMEM);
    cudaFuncSetAttribute(attn_pv2,
        cudaFuncAttributeMaxDynamicSharedMemorySize, PV_SMEM);

    // pre-round inputs + weights to tf32 bits
    round3<<<dim3(MTOT * DIM / 4 / 256, 3), 256>>>(query, key, value, prq, prk, prv);
    round4<<<dim3(DIM * DIM / 4 / 256, 4), 256>>>(Wq, Wk, Wv, Wo, pw);

    dim3 gqkv(DIM / 128, MTOT / 128, 3);   // (8, 32, 3)
    gemm_qkv<<<gqkv, 256, GEMM_SMEM>>>(prq, prk, prv, pw, bq, bk, bv, pq, pk, pv);

    attn_scores_v3<<<dim3(SEQ / 128, SEQ / 128, BH), 256, SC_SMEM>>>(score);
    combine_stats<<<NROWS / 256, 256>>>();
    attn_pv2<<<dim3(SEQ / 128, BH), 256, PV_SMEM>>>(score);

    dim3 gp(DIM / 128, MTOT / 128);   // (8, 32)
    gemm_cpa<<<gp, 256, GEMM_SMEM>>>(pbl, pw + 3 * DIM * DIM, bo, out, MTOT, DIM, DIM, 0);
}

// round 15
// speedup vs baseline: 1.1898x; 1.0296x over previous
#include <cuda_runtime.h>
#include <math.h>
#include <stdint.h>

#define BSZ 2
#define SEQ 2048
#define DIM 1024
#define NH  16
#define DK  64
#define BH  (BSZ*NH)   // 32
#define MTOT (BSZ*SEQ) // 4096
#define NROWS (BH*SEQ) // 65536
#define NCT  16        // col tiles of 128 per row

// Scratch (allocation-free rule: __device__ globals)
__device__ float g_q [BSZ*SEQ*DIM];
__device__ float g_k [BSZ*SEQ*DIM];
__device__ float g_v [BSZ*SEQ*DIM];
__device__ float g_bl[BSZ*SEQ*DIM];
__device__ float g_rq[BSZ*SEQ*DIM];     // tf32-rounded inputs
__device__ float g_rk[BSZ*SEQ*DIM];
__device__ float g_rv[BSZ*SEQ*DIM];
__device__ float g_w [4*DIM*DIM];       // tf32-rounded weights
__device__ float g_smax  [NROWS*NCT];
__device__ float g_ssum  [NROWS*NCT];
__device__ float g_factor[NROWS*NCT];

// ---------------------------------------------------------------------------
// helpers
// ---------------------------------------------------------------------------
__device__ __forceinline__ unsigned f2tf(float x) {
    unsigned r;
    asm("cvt.rna.tf32.f32 %0, %1;" : "=r"(r) : "f"(x));
    return r;
}

__device__ __forceinline__ void mma_tf32(float c[4],
    unsigned a0, unsigned a1, unsigned a2, unsigned a3,
    unsigned b0, unsigned b1)
{
    asm volatile(
        "mma.sync.aligned.m16n8k8.row.col.f32.tf32.tf32.f32 "
        "{%0,%1,%2,%3}, {%4,%5,%6,%7}, {%8,%9}, {%0,%1,%2,%3};\n"
        : "+f"(c[0]), "+f"(c[1]), "+f"(c[2]), "+f"(c[3])
        : "r"(a0), "r"(a1), "r"(a2), "r"(a3), "r"(b0), "r"(b1));
}

__device__ __forceinline__ unsigned smem_u32(const void* p) {
    unsigned a;
    asm("{ .reg .u64 t; cvta.to.shared.u64 t, %1; cvt.u32.u64 %0, t; }"
        : "=r"(a) : "l"(p));
    return a;
}

#define CPA_COMMIT() asm volatile("cp.async.commit_group;" ::: "memory")
#define CPA_WAIT1()  asm volatile("cp.async.wait_group 1;" ::: "memory")
#define CPA_WAIT0()  asm volatile("cp.async.wait_group 0;" ::: "memory")

__device__ __forceinline__ void cpa16(const void* smem_dst, const float* gsrc) {
    unsigned sa = smem_u32(smem_dst);
    asm volatile("cp.async.cg.shared.global [%0], [%1], 16;"
                 :: "r"(sa), "l"(gsrc) : "memory");
}

// ---------------------------------------------------------------------------
// pre-round kernels (tf32 bits, idempotent w.r.t. later MMA use)
// ---------------------------------------------------------------------------
__global__ __launch_bounds__(256) void round3(
    const float* __restrict__ a, const float* __restrict__ b,
    const float* __restrict__ c,
    float* __restrict__ da, float* __restrict__ db, float* __restrict__ dc)
{
    const float* s; float* d;
    if      (blockIdx.y == 0) { s = a; d = da; }
    else if (blockIdx.y == 1) { s = b; d = db; }
    else                      { s = c; d = dc; }
    int i = blockIdx.x * 256 + threadIdx.x;
    float4 v = ((const float4*)s)[i];
    uint4 o = make_uint4(f2tf(v.x), f2tf(v.y), f2tf(v.z), f2tf(v.w));
    ((uint4*)d)[i] = o;
}

__global__ __launch_bounds__(256) void round4(
    const float* __restrict__ a, const float* __restrict__ b,
    const float* __restrict__ c, const float* __restrict__ d,
    float* __restrict__ dst)
{
    const float* s;
    if      (blockIdx.y == 0) s = a;
    else if (blockIdx.y == 1) s = b;
    else if (blockIdx.y == 2) s = c;
    else                      s = d;
    int i = blockIdx.x * 256 + threadIdx.x;
    float4 v = ((const float4*)s)[i];
    uint4 o = make_uint4(f2tf(v.x), f2tf(v.y), f2tf(v.z), f2tf(v.w));
    ((uint4*)(dst + (size_t)blockIdx.y * DIM * DIM))[i] = o;
}

// ---------------------------------------------------------------------------
// GEMM with BK=32 K-chunks, 3-stage cp.async ring, one barrier per chunk.
// ---------------------------------------------------------------------------
#define TP2 36   // floats per padded row (32 data + 4 pad), conflict-free

// cp.async one 128x32 f32 tile; 256 threads, 4 float4 each.
__device__ __forceinline__ void cpa_tile32(
    float (*dst)[TP2], const float* __restrict__ src, int lda, int tid)
{
    #pragma unroll
    for (int i = 0; i < 4; i++) {
        int id = tid + i * 256;       // 0..1023
        int r  = id >> 3;             // 0..127
        int c4 = (id & 7) << 2;       // 0,4,...,28
        cpa16(&dst[r][c4], src + (size_t)r * lda + c4);
    }
}

// One 32-K chunk of MMAs; inputs PRE-ROUNDED tf32 bits (no cvt).
__device__ __forceinline__ void tile_mma32(
    const float (*As)[TP2], const float (*Bs)[TP2],
    float acc[4][4][4], int wm, int wn, int grp, int qd)
{
    #pragma unroll
    for (int kk = 0; kk < 32; kk += 8) {
        unsigned a[4][4], b[4][2];
        #pragma unroll
        for (int mi = 0; mi < 4; mi++) {
            int m = wm * 64 + mi * 16;
            a[mi][0] = __float_as_uint(As[m + grp    ][kk + qd    ]);
            a[mi][1] = __float_as_uint(As[m + grp + 8][kk + qd    ]);
            a[mi][2] = __float_as_uint(As[m + grp    ][kk + qd + 4]);
            a[mi][3] = __float_as_uint(As[m + grp + 8][kk + qd + 4]);
        }
        #pragma unroll
        for (int ni = 0; ni < 4; ni++) {
            int n = wn * 32 + ni * 8 + grp;
            b[ni][0] = __float_as_uint(Bs[n][kk + qd    ]);
            b[ni][1] = __float_as_uint(Bs[n][kk + qd + 4]);
        }
        #pragma unroll
        for (int mi = 0; mi < 4; mi++)
            #pragma unroll
            for (int ni = 0; ni < 4; ni++)
                mma_tf32(acc[mi][ni], a[mi][0], a[mi][1], a[mi][2], a[mi][3],
                         b[ni][0], b[ni][1]);
    }
}

// 3-stage ring over nk 32-K chunks (nk >= 3). One barrier per chunk.
// Safety: prefetch at iter t writes slot (t+2)%3, last read at iter t-1;
// the top-of-iteration barrier (before mma t) orders those reads first.
__device__ __forceinline__ void cpa_loop32(
    const float* __restrict__ A, int lda,
    const float* __restrict__ B, int ldb, int nk,
    float (*As)[128][TP2], float (*Bs)[128][TP2],
    float acc[4][4][4], int tid, int wm, int wn, int grp, int qd)
{
    cpa_tile32(As[0], A, lda, tid);
    cpa_tile32(Bs[0], B, ldb, tid);
    CPA_COMMIT();
    cpa_tile32(As[1], A + 32, lda, tid);
    cpa_tile32(Bs[1], B + 32, ldb, tid);
    CPA_COMMIT();

    int cur = 0;
    for (int t = 0; t < nk; t++) {
        if (t < nk - 1) CPA_WAIT1(); else CPA_WAIT0();
        __syncthreads();
        tile_mma32(As[cur], Bs[cur], acc, wm, wn, grp, qd);
        if (t + 2 < nk) {
            int nxt = cur + 2; if (nxt >= 3) nxt -= 3;
            cpa_tile32(As[nxt], A + (t + 2) * 32, lda, tid);
            cpa_tile32(Bs[nxt], B + (t + 2) * 32, ldb, tid);
            CPA_COMMIT();
        }
        if (++cur == 3) cur = 0;
    }
}

#define GEMM_SMEM (3 * 128 * TP2 * 4 * 2)   // 110592 bytes

__device__ __forceinline__ void gemm_body(
    const float* __restrict__ A, const float* __restrict__ W,
    const float* __restrict__ bias, float* __restrict__ C,
    int M, int N, int K, int round_out, float* sm)
{
    float (*As)[128][TP2] = (float (*)[128][TP2])sm;
    float (*Bs)[128][TP2] = (float (*)[128][TP2])(sm + 3 * 128 * TP2);

    int tid = threadIdx.x;
    int warp = tid >> 5, lane = tid & 31;
    int wm = warp >> 2, wn = warp & 3;
    int grp = lane >> 2, qd = lane & 3;

    const float* Ab = A + (size_t)(blockIdx.y * 128) * K;
    const float* Wb = W + (size_t)(blockIdx.x * 128) * K;
    float acc[4][4][4] = {};
    cpa_loop32(Ab, K, Wb, K, K / 32, As, Bs, acc, tid, wm, wn, grp, qd);

    int row0 = blockIdx.y * 128 + wm * 64;
    int col0 = blockIdx.x * 128 + wn * 32;
    #pragma unroll
    for (int mi = 0; mi < 4; mi++) {
        #pragma unroll
        for (int ni = 0; ni < 4; ni++) {
            int r  = row0 + mi * 16 + grp;
            int cc = col0 + ni * 8 + qd * 2;
            float b0 = bias[cc], b1 = bias[cc + 1];
            float v00 = acc[mi][ni][0] + b0, v01 = acc[mi][ni][1] + b1;
            float v10 = acc[mi][ni][2] + b0, v11 = acc[mi][ni][3] + b1;
            if (round_out) {
                v00 = __uint_as_float(f2tf(v00)); v01 = __uint_as_float(f2tf(v01));
                v10 = __uint_as_float(f2tf(v10)); v11 = __uint_as_float(f2tf(v11));
            }
            *(float2*)(C + (size_t)r * N + cc)       = make_float2(v00, v01);
            *(float2*)(C + (size_t)(r + 8) * N + cc) = make_float2(v10, v11);
        }
    }
}

// QKV fused: grid.z selects which projection this block computes.
__global__ __launch_bounds__(256, 2) void gemm_qkv(
    const float* __restrict__ rq, const float* __restrict__ rk,
    const float* __restrict__ rv, const float* __restrict__ w,
    const float* __restrict__ bq, const float* __restrict__ bk,
    const float* __restrict__ bv,
    float* __restrict__ oq, float* __restrict__ ok, float* __restrict__ ov)
{
    extern __shared__ float sm[];
    const float* A; const float* bias; float* C;
    int z = blockIdx.z;
    if      (z == 0) { A = rq; bias = bq; C = oq; }
    else if (z == 1) { A = rk; bias = bk; C = ok; }
    else             { A = rv; bias = bv; C = ov; }
    gemm_body(A, w + (size_t)z * DIM * DIM, bias, C, MTOT, DIM, DIM, 1, sm);
}

__global__ __launch_bounds__(256, 2) void gemm_cpa(
    const float* __restrict__ A, const float* __restrict__ W,
    const float* __restrict__ bias, float* __restrict__ C,
    int M, int N, int K, int round_out)
{
    extern __shared__ float sm[];
    gemm_body(A, W, bias, C, M, N, K, round_out, sm);
}

// ---------------------------------------------------------------------------
// scores: Q,K tiles fully resident (K=64), inputs pre-rounded (no cvt).
// Writes e = exp(x/8 - m_tile) + per-row-tile (max,sum) partials.
// ---------------------------------------------------------------------------
#define QPAD 68
#define SC_SMEM (2 * 128 * QPAD * 4)   // 69632

__global__ __launch_bounds__(256, 2) void attn_scores_v3(float* __restrict__ score)
{
    extern __shared__ float sm[];
    float (*Qs)[QPAD] = (float (*)[QPAD])sm;
    float (*Ks)[QPAD] = (float (*)[QPAD])(sm + 128 * QPAD);
    float (*rstat)[4] = (float (*)[4])sm;   // reuse after mainloop

    int tid = threadIdx.x;
    int warp = tid >> 5, lane = tid & 31;
    int wm = warp >> 2, wn = warp & 3;
    int grp = lane >> 2, qd = lane & 3;
    int bh = blockIdx.z, b = bh >> 4, h = bh & 15;

    const float* qb = g_q + (size_t)b * SEQ * DIM + (size_t)(blockIdx.y * 128) * DIM + h * DK;
    const float* kb = g_k + (size_t)b * SEQ * DIM + (size_t)(blockIdx.x * 128) * DIM + h * DK;

    #pragma unroll
    for (int i = 0; i < 8; i++) {
        int id = tid + i * 256;       // 0..2047
        int r  = id >> 4;             // 0..127
        int c4 = (id & 15) << 2;      // 0..60
        cpa16(&Qs[r][c4], qb + (size_t)r * DIM + c4);
    }
    #pragma unroll
    for (int i = 0; i < 8; i++) {
        int id = tid + i * 256;
        int r  = id >> 4;
        int c4 = (id & 15) << 2;
        cpa16(&Ks[r][c4], kb + (size_t)r * DIM + c4);
    }
    CPA_COMMIT();
    CPA_WAIT0();
    __syncthreads();

    float acc[4][4][4] = {};
    #pragma unroll
    for (int kk8 = 0; kk8 < 64; kk8 += 8) {
        unsigned a[4][4], bf[4][2];
        #pragma unroll
        for (int mi = 0; mi < 4; mi++) {
            int m = wm * 64 + mi * 16;
            a[mi][0] = __float_as_uint(Qs[m + grp    ][kk8 + qd    ]);
            a[mi][1] = __float_as_uint(Qs[m + grp + 8][kk8 + qd    ]);
            a[mi][2] = __float_as_uint(Qs[m + grp    ][kk8 + qd + 4]);
            a[mi][3] = __float_as_uint(Qs[m + grp + 8][kk8 + qd + 4]);
        }
        #pragma unroll
        for (int ni = 0; ni < 4; ni++) {
            int n = wn * 32 + ni * 8 + grp;
            bf[ni][0] = __float_as_uint(Ks[n][kk8 + qd    ]);
            bf[ni][1] = __float_as_uint(Ks[n][kk8 + qd + 4]);
        }
        #pragma unroll
        for (int mi = 0; mi < 4; mi++)
            #pragma unroll
            for (int ni = 0; ni < 4; ni++)
                mma_tf32(acc[mi][ni], a[mi][0], a[mi][1], a[mi][2], a[mi][3],
                         bf[ni][0], bf[ni][1]);
    }
    __syncthreads();   // tiles dead; rstat aliases smem

    const float alpha = 0.125f;
    #pragma unroll
    for (int mi = 0; mi < 4; mi++)
        #pragma unroll
        for (int ni = 0; ni < 4; ni++)
            #pragma unroll
            for (int j = 0; j < 4; j++)
                acc[mi][ni][j] *= alpha;

    float msel[4][2];
    #pragma unroll
    for (int mi = 0; mi < 4; mi++) {
        float mA = -1e30f, mB = -1e30f;
        #pragma unroll
        for (int ni = 0; ni < 4; ni++) {
            mA = fmaxf(mA, fmaxf(acc[mi][ni][0], acc[mi][ni][1]));
            mB = fmaxf(mB, fmaxf(acc[mi][ni][2], acc[mi][ni][3]));
        }
        mA = fmaxf(mA, __shfl_xor_sync(0xffffffffu, mA, 1));
        mA = fmaxf(mA, __shfl_xor_sync(0xffffffffu, mA, 2));
        mB = fmaxf(mB, __shfl_xor_sync(0xffffffffu, mB, 1));
        mB = fmaxf(mB, __shfl_xor_sync(0xffffffffu, mB, 2));
        int rA = wm * 64 + mi * 16 + grp;
        if (qd == 0) { rstat[rA][wn] = mA; rstat[rA + 8][wn] = mB; }
    }
    __syncthreads();
    #pragma unroll
    for (int mi = 0; mi < 4; mi++) {
        int rA = wm * 64 + mi * 16 + grp;
        msel[mi][0] = fmaxf(fmaxf(rstat[rA][0],     rstat[rA][1]),
                            fmaxf(rstat[rA][2],     rstat[rA][3]));
        msel[mi][1] = fmaxf(fmaxf(rstat[rA + 8][0], rstat[rA + 8][1]),
                            fmaxf(rstat[rA + 8][2], rstat[rA + 8][3]));
    }
    __syncthreads();

    float ssel[4][2];
    #pragma unroll
    for (int mi = 0; mi < 4; mi++) {
        float sA = 0.f, sB = 0.f;
        #pragma unroll
        for (int ni = 0; ni < 4; ni++) {
            acc[mi][ni][0] = __expf(acc[mi][ni][0] - msel[mi][0]);
            acc[mi][ni][1] = __expf(acc[mi][ni][1] - msel[mi][0]);
            acc[mi][ni][2] = __expf(acc[mi][ni][2] - msel[mi][1]);
            acc[mi][ni][3] = __expf(acc[mi][ni][3] - msel[mi][1]);
            sA += acc[mi][ni][0] + acc[mi][ni][1];
            sB += acc[mi][ni][2] + acc[mi][ni][3];
        }
        sA += __shfl_xor_sync(0xffffffffu, sA, 1);
        sA += __shfl_xor_sync(0xffffffffu, sA, 2);
        sB += __shfl_xor_sync(0xffffffffu, sB, 1);
        sB += __shfl_xor_sync(0xffffffffu, sB, 2);
        int rA = wm * 64 + mi * 16 + grp;
        if (qd == 0) { rstat[rA][wn] = sA; rstat[rA + 8][wn] = sB; }
    }
    __syncthreads();
    #pragma unroll
    for (int mi = 0; mi < 4; mi++) {
        int rA = wm * 64 + mi * 16 + grp;
        ssel[mi][0] = (rstat[rA][0]     + rstat[rA][1])
                    + (rstat[rA][2]     + rstat[rA][3]);
        ssel[mi][1] = (rstat[rA + 8][0] + rstat[rA + 8][1])
                    + (rstat[rA + 8][2] + rstat[rA + 8][3]);
    }

    float* ob = score + (size_t)bh * SEQ * SEQ;
    int row0 = blockIdx.y * 128 + wm * 64;
    int col0 = blockIdx.x * 128 + wn * 32;
    #pragma unroll
    for (int mi = 0; mi < 4; mi++) {
        #pragma unroll
        for (int ni = 0; ni < 4; ni++) {
            int r  = row0 + mi * 16 + grp;
            int cc = col0 + ni * 8 + qd * 2;
            *(float2*)(ob + (size_t)r * SEQ + cc) =
                make_float2(acc[mi][ni][0], acc[mi][ni][1]);
            *(float2*)(ob + (size_t)(r + 8) * SEQ + cc) =
                make_float2(acc[mi][ni][2], acc[mi][ni][3]);
        }
    }

    if (wn == 0 && qd == 0) {
        #pragma unroll
        for (int mi = 0; mi < 4; mi++) {
            #pragma unroll
            for (int half = 0; half < 2; half++) {
                int rowg = blockIdx.y * 128 + wm * 64 + mi * 16 + half * 8 + grp;
                size_t idx = ((size_t)(bh << 11) + rowg) * NCT + blockIdx.x;
                g_smax[idx] = msel[mi][half];
                g_ssum[idx] = ssel[mi][half];
            }
        }
    }
}

// ---------------------------------------------------------------------------
__global__ __launch_bounds__(256) void combine_stats()
{
    int gid = blockIdx.x * 256 + threadIdx.x;
    const float* mx = g_smax + (size_t)gid * NCT;
    const float* smv = g_ssum + (size_t)gid * NCT;
    float mv[NCT];
    float m = -1e30f;
    #pragma unroll
    for (int i = 0; i < NCT; i++) { mv[i] = mx[i]; m = fmaxf(m, mv[i]); }
    float s = 0.f;
    float ev[NCT];
    #pragma unroll
    for (int i = 0; i < NCT; i++) { ev[i] = __expf(mv[i] - m); s += smv[i] * ev[i]; }
    float inv = 1.0f / s;
    #pragma unroll
    for (int i = 0; i < NCT; i++) g_factor[(size_t)gid * NCT + i] = ev[i] * inv;
}

// ---------------------------------------------------------------------------
// PV v2: 256 threads, warps 2(M)x4(N) warp tile 64x16, CHK=32.
// Reads e, p = e*factor, writes final p in place, accumulates P@V.
// ---------------------------------------------------------------------------
#define CHK2 32
#define PVP 36
#define PV_SMEM ((128 * PVP + 2 * CHK2 * 72) * 4)   // 36864 bytes

__global__ __launch_bounds__(256, 2) void attn_pv2(float* __restrict__ score)
{
    extern __shared__ float smraw[];
    unsigned (*Ps)[PVP]       = (unsigned (*)[PVP])smraw;
    unsigned (*Vs)[CHK2][72]  = (unsigned (*)[CHK2][72])(smraw + 128 * PVP);

    int tid = threadIdx.x;
    int warp = tid >> 5, lane = tid & 31;
    int wm = warp >> 2, wn = warp & 3;     // 2 x 4
    int grp = lane >> 2, qd = lane & 3;
    int bh = blockIdx.y, b = bh >> 4, h = bh & 15;
    int row0 = blockIdx.x * 128;

    float* pb = score + (size_t)bh * SEQ * SEQ + (size_t)row0 * SEQ;
    const float* vb = g_v + (size_t)b * SEQ * DIM + h * DK;
    const float* fb = g_factor + ((size_t)(bh << 11) + row0) * NCT;

    float acc[4][2][4] = {};
    float4 pe[4]; float pf[4]; float4 pvv[2];

    // prologue: chunk 0
    #pragma unroll
    for (int i = 0; i < 4; i++) {
        int id = tid + i * 256;       // 0..1023
        int r  = id >> 3;             // 0..127
        int c4 = (id & 7) << 2;       // 0..28
        pe[i] = *(const float4*)(pb + (size_t)r * SEQ + c4);
        pf[i] = fb[r * NCT + 0];
    }
    #pragma unroll
    for (int i = 0; i < 2; i++) {
        int id = tid + i * 256;       // 0..511
        int r  = id >> 4;             // 0..31
        int c4 = (id & 15) << 2;
        pvv[i] = *(const float4*)(vb + (size_t)r * DIM + c4);
    }
    #pragma unroll
    for (int i = 0; i < 4; i++) {
        int id = tid + i * 256;
        int r  = id >> 3;
        int c4 = (id & 7) << 2;
        float4 p = make_float4(pe[i].x * pf[i], pe[i].y * pf[i],
                               pe[i].z * pf[i], pe[i].w * pf[i]);
        *(float4*)(pb + (size_t)r * SEQ + c4) = p;
        *(uint4*)&Ps[r][c4] = make_uint4(f2tf(p.x), f2tf(p.y), f2tf(p.z), f2tf(p.w));
    }
    #pragma unroll
    for (int i = 0; i < 2; i++) {
        int id = tid + i * 256;
        int r  = id >> 4;
        int c4 = (id & 15) << 2;
        *(uint4*)&Vs[0][r][c4] = make_uint4(
            __float_as_uint(pvv[i].x), __float_as_uint(pvv[i].y),
            __float_as_uint(pvv[i].z), __float_as_uint(pvv[i].w));
    }
    __syncthreads();

    const int NTCH = SEQ / CHK2;   // 64
    for (int t = 0; t < NTCH; t++) {
        int cur = t & 1;
        if (t + 1 < NTCH) {
            int ct = (t + 1) >> 2;
            #pragma unroll
            for (int i = 0; i < 4; i++) {
                int id = tid + i * 256;
                int r  = id >> 3;
                int c4 = (id & 7) << 2;
                pe[i] = *(const float4*)(pb + (size_t)r * SEQ + (t + 1) * CHK2 + c4);
                pf[i] = fb[r * NCT + ct];
            }
            #pragma unroll
            for (int i = 0; i < 2; i++) {
                int id = tid + i * 256;
                int r  = id >> 4;
                int c4 = (id & 15) << 2;
                pvv[i] = *(const float4*)(vb + (size_t)((t + 1) * CHK2 + r) * DIM + c4);
            }
        }

        // PV MMA: acc += P[128xCHK2] @ V[CHK2x64]; warp tile 64x16
        #pragma unroll
        for (int kk = 0; kk < CHK2; kk += 8) {
            unsigned a[4][4], bf[2][2];
            #pragma unroll
            for (int mi = 0; mi < 4; mi++) {
                int m = wm * 64 + mi * 16;
                a[mi][0] = Ps[m + grp    ][kk + qd    ];
                a[mi][1] = Ps[m + grp + 8][kk + qd    ];
                a[mi][2] = Ps[m + grp    ][kk + qd + 4];
                a[mi][3] = Ps[m + grp + 8][kk + qd + 4];
            }
            #pragma unroll
            for (int ni = 0; ni < 2; ni++) {
                int n = wn * 16 + ni * 8 + grp;
                bf[ni][0] = Vs[cur][kk + qd    ][n];
                bf[ni][1] = Vs[cur][kk + qd + 4][n];
            }
            #pragma unroll
            for (int mi = 0; mi < 4; mi++)
                #pragma unroll
                for (int ni = 0; ni < 2; ni++)
                    mma_tf32(acc[mi][ni], a[mi][0], a[mi][1], a[mi][2], a[mi][3],
                             bf[ni][0], bf[ni][1]);
        }
        __syncthreads();   // MMA reads of Ps/Vs[cur] done

        if (t + 1 < NTCH) {
            int nxt = cur ^ 1;
            #pragma unroll
            for (int i = 0; i < 4; i++) {
                int id = tid + i * 256;
                int r  = id >> 3;
                int c4 = (id & 7) << 2;
                float4 p = make_float4(pe[i].x * pf[i], pe[i].y * pf[i],
                                       pe[i].z * pf[i], pe[i].w * pf[i]);
                *(float4*)(pb + (size_t)r * SEQ + (t + 1) * CHK2 + c4) = p;
                *(uint4*)&Ps[r][c4] = make_uint4(f2tf(p.x), f2tf(p.y), f2tf(p.z), f2tf(p.w));
            }
            #pragma unroll
            for (int i = 0; i < 2; i++) {
                int id = tid + i * 256;
                int r  = id >> 4;
                int c4 = (id & 15) << 2;
                *(uint4*)&Vs[nxt][r][c4] = make_uint4(
                    __float_as_uint(pvv[i].x), __float_as_uint(pvv[i].y),
                    __float_as_uint(pvv[i].z), __float_as_uint(pvv[i].w));
            }
            __syncthreads();   // new Ps/Vs visible
        }
    }

    // store blended pre-rounded to tf32 bits for the cvt-free out-proj GEMM
    float* ob = g_bl + (size_t)b * SEQ * DIM;
    int r0 = row0 + wm * 64;
    int c0 = h * DK + wn * 16;
    #pragma unroll
    for (int mi = 0; mi < 4; mi++) {
        #pragma unroll
        for (int ni = 0; ni < 2; ni++) {
            int r  = r0 + mi * 16 + grp;
            int cc = c0 + ni * 8 + qd * 2;
            float2 o0 = make_float2(__uint_as_float(f2tf(acc[mi][ni][0])),
                                    __uint_as_float(f2tf(acc[mi][ni][1])));
            float2 o1 = make_float2(__uint_as_float(f2tf(acc[mi][ni][2])),
                                    __uint_as_float(f2tf(acc[mi][ni][3])));
            *(float2*)(ob + (size_t)r * DIM + cc)       = o0;
            *(float2*)(ob + (size_t)(r + 8) * DIM + cc) = o1;
        }
    }
}

// ---------------------------------------------------------------------------
extern "C" void kernel_launch(void* const* d_in, const int* in_sizes, int n_in,
                              void* d_out, int out_size)
{
    const float* query = (const float*)d_in[0];
    const float* key   = (const float*)d_in[1];
    const float* value = (const float*)d_in[2];
    const float* Wq    = (const float*)d_in[3];
    const float* bq    = (const float*)d_in[4];
    const float* Wk    = (const float*)d_in[5];
    const float* bk    = (const float*)d_in[6];
    const float* Wv    = (const float*)d_in[7];
    const float* bv    = (const float*)d_in[8];
    const float* Wo    = (const float*)d_in[9];
    const float* bo    = (const float*)d_in[10];

    float* out   = (float*)d_out;                          // [B,S,D]
    float* score = out + (size_t)BSZ * SEQ * DIM;          // [B,H,S,S]

    float *pq, *pk, *pv, *pbl, *prq, *prk, *prv, *pw;
    cudaGetSymbolAddress((void**)&pq,  g_q);
    cudaGetSymbolAddress((void**)&pk,  g_k);
    cudaGetSymbolAddress((void**)&pv,  g_v);
    cudaGetSymbolAddress((void**)&pbl, g_bl);
    cudaGetSymbolAddress((void**)&prq, g_rq);
    cudaGetSymbolAddress((void**)&prk, g_rk);
    cudaGetSymbolAddress((void**)&prv, g_rv);
    cudaGetSymbolAddress((void**)&pw,  g_w);

    cudaFuncSetAttribute(gemm_cpa,
        cudaFuncAttributeMaxDynamicSharedMemorySize, GEMM_SMEM);
    cudaFuncSetAttribute(gemm_qkv,
        cudaFuncAttributeMaxDynamicSharedMemorySize, GEMM_SMEM);
    cudaFuncSetAttribute(attn_scores_v3,
        cudaFuncAttributeMaxDynamicSharedMemorySize, SC_SMEM);
    cudaFuncSetAttribute(attn_pv2,
        cudaFuncAttributeMaxDynamicSharedMemorySize, PV_SMEM);

    // pre-round inputs + weights to tf32 bits
    round3<<<dim3(MTOT * DIM / 4 / 256, 3), 256>>>(query, key, value, prq, prk, prv);
    round4<<<dim3(DIM * DIM / 4 / 256, 4), 256>>>(Wq, Wk, Wv, Wo, pw);

    dim3 gqkv(DIM / 128, MTOT / 128, 3);   // (8, 32, 3)
    gemm_qkv<<<gqkv, 256, GEMM_SMEM>>>(prq, prk, prv, pw, bq, bk, bv, pq, pk, pv);

    attn_scores_v3<<<dim3(SEQ / 128, SEQ / 128, BH), 256, SC_SMEM>>>(score);
    combine_stats<<<NROWS / 256, 256>>>();
    attn_pv2<<<dim3(SEQ / 128, BH), 256, PV_SMEM>>>(score);

    dim3 gp(DIM / 128, MTOT / 128);   // (8, 32)
    gemm_cpa<<<gp, 256, GEMM_SMEM>>>(pbl, pw + 3 * DIM * DIM, bo, out, MTOT, DIM, DIM, 0);
}